// round 5
// baseline (speedup 1.0000x reference)
#include <cuda_runtime.h>
#include <cuda_fp16.h>
#include <math.h>

#define NN 2048
#define TT 20
#define KK 32
#define CC 32
#define OO 64
#define G4 256   // 4*OO
#define AG 8     // agents per k4 block

// Scratch (static device globals; no runtime allocation)
__device__ float   g_z[TT * NN * OO];       // z[t][n][o] f32 (center term)
__device__ __half2 g_zh[TT * NN * (OO/2)];  // z fp16 copy (gather/max term)
__device__ float   g_gates[TT * NN * G4];   // gates_x[t][n][0..255]

typedef unsigned long long u64;

__device__ __forceinline__ void ffma2(u64& d, u64 a, u64 b) {
    asm("fma.rn.f32x2 %0, %1, %2, %0;" : "+l"(d) : "l"(a), "l"(b));
}
__device__ __forceinline__ float2 unpack2(u64 v) {
    float2 r;
    asm("mov.b64 {%0,%1}, %2;" : "=f"(r.x), "=f"(r.y) : "l"(v));
    return r;
}
__device__ __forceinline__ u64 pack2(float x, float y) {
    u64 r;
    asm("mov.b64 %0, {%1,%2};" : "=l"(r) : "f"(x), "f"(y));
    return r;
}

// NaN-safe fast sigmoid / tanh (rel err ~1e-7, 2 MUFU each)
__device__ __forceinline__ float sigf(float x) {
    return __fdividef(1.0f, 1.0f + __expf(-x));
}
__device__ __forceinline__ float tanhf_fast(float x) {
    return 1.0f - __fdividef(2.0f, __expf(2.0f * x) + 1.0f);
}

// ---------------------------------------------------------------------------
// K1: z[t][n][o] = sum_c x[n][t][c] * conv_w[o][c]; writes f32 + fp16 copies.
// ---------------------------------------------------------------------------
__global__ __launch_bounds__(256) void k1_project(const float* __restrict__ x,
                                                  const float* __restrict__ conv_w) {
    __shared__ float cwT[CC * OO];      // cwT[c*64 + o]
    __shared__ float xs[8][CC];

    const int tid = threadIdx.x;
    for (int e = tid; e < OO * CC; e += 256) {
        int o = e >> 5, c = e & 31;
        cwT[c * OO + o] = conv_w[e];
    }

    const int r = tid >> 5, lane = tid & 31;
    const int row = (blockIdx.x << 3) + r;          // row = t*N + n
    const int t = row >> 11, n = row & (NN - 1);
    xs[r][lane] = x[((n * TT + t) << 5) + lane];
    __syncthreads();

    float2 acc = make_float2(0.f, 0.f);
    const float2* cwT2 = (const float2*)cwT;
#pragma unroll
    for (int c = 0; c < CC; c++) {
        float xv = xs[r][c];
        float2 w2 = cwT2[c * 32 + lane];
        acc.x = fmaf(xv, w2.x, acc.x);
        acc.y = fmaf(xv, w2.y, acc.y);
    }
    ((float2*)g_z)[row * 32 + lane] = acc;
    g_zh[row * 32 + lane] = __floats2half2_rn(acc.x, acc.y);
}

// ---------------------------------------------------------------------------
// K23 (fused gather-max + input GEMM):
// Phase A: block owns 32 rows (t,n); each warp gather-maxes 4 rows (fp16
//          neighbor z, f32 center z + bias) and writes feat to SMEM only.
// Phase B: gates_x[row][o] = feat[row][:] . w_ih[o][:] + bias, 4-row unroll
//          (4 independent f32x2 accumulator chains), broadcast LDS.128 feat.
// feat never touches global memory.
// ---------------------------------------------------------------------------
__global__ __launch_bounds__(256) void k23_feat_gates(const int* __restrict__ A,
                                                      const float* __restrict__ conv_b,
                                                      const float* __restrict__ w_ih,
                                                      const float* __restrict__ b_ih,
                                                      const float* __restrict__ b_hh) {
    __shared__ u64 fs[32 * 32];  // 32 rows x 32 u64 (64 floats) of feat

    const int tid = threadIdx.x;
    const int lane = tid & 31;
    const int wrp = tid >> 5;
    const int row0 = blockIdx.x << 5;   // first global row (row = t*N + n)

    // ---- preload w_ih row into regs (overlaps phase A) ----
    u64 w[32];
    const u64* wp = ((const u64*)w_ih) + tid * 32;
#pragma unroll
    for (int j = 0; j < 32; j++) w[j] = wp[j];
    const float bias = b_ih[tid] + b_hh[tid];

    const float2 cb = ((const float2*)conv_b)[lane];

    // ---- Phase A: gather-max for this warp's 4 rows ----
#pragma unroll
    for (int rr = 0; rr < 4; rr++) {
        const int row = row0 + (wrp << 2) + rr;
        const int t = row >> 11;
        const int nb = A[(row << 5) + lane];

        __half2 m = __float2half2_rn(-60000.f);
#pragma unroll
        for (int k = 0; k < KK; k++) {
            int r = __shfl_sync(0xffffffffu, nb, k);
            __half2 v = __ldg(&g_zh[(((t << 11) + r) << 5) + lane]);
            m = __hmax2(m, v);
        }
        float2 mf = __half22float2(m);
        float2 zc = ((const float2*)g_z)[(row << 5) + lane];
        fs[((wrp << 2) + rr) * 32 + lane] = pack2(mf.x - zc.x + cb.x,
                                                  mf.y - zc.y + cb.y);
    }
    __syncthreads();

    // ---- Phase B: GEMM, 4 rows per iteration (4 acc chains) ----
    const ulonglong2* fs2 = (const ulonglong2*)fs;
    for (int r = 0; r < 32; r += 4) {
        u64 a0 = 0ull, a1 = 0ull, a2 = 0ull, a3 = 0ull;
#pragma unroll
        for (int j = 0; j < 16; j++) {
            u64 w0 = w[2 * j], w1 = w[2 * j + 1];
            ulonglong2 f0 = fs2[(r + 0) * 16 + j];
            ulonglong2 f1 = fs2[(r + 1) * 16 + j];
            ulonglong2 f2 = fs2[(r + 2) * 16 + j];
            ulonglong2 f3 = fs2[(r + 3) * 16 + j];
            ffma2(a0, w0, f0.x); ffma2(a0, w1, f0.y);
            ffma2(a1, w0, f1.x); ffma2(a1, w1, f1.y);
            ffma2(a2, w0, f2.x); ffma2(a2, w1, f2.y);
            ffma2(a3, w0, f3.x); ffma2(a3, w1, f3.y);
        }
        float2 v0 = unpack2(a0), v1 = unpack2(a1);
        float2 v2 = unpack2(a2), v3 = unpack2(a3);
        g_gates[(size_t)(row0 + r + 0) * G4 + tid] = v0.x + v0.y + bias;
        g_gates[(size_t)(row0 + r + 1) * G4 + tid] = v1.x + v1.y + bias;
        g_gates[(size_t)(row0 + r + 2) * G4 + tid] = v2.x + v2.y + bias;
        g_gates[(size_t)(row0 + r + 3) * G4 + tid] = v3.x + v3.y + bias;
    }
}

// ---------------------------------------------------------------------------
// K4: persistent LSTM. 256 blocks x 256 threads; block owns 8 agents for all
// 20 steps; ~2 blocks/SM. Matvec: thread owns gate col o for all 8 agents,
// w_hh row in 32 u64 regs, h broadcast via LDS.128, packed f32x2 FMA.
// Update: thread owns (agent, 2 channels), c in registers.
// ---------------------------------------------------------------------------
__global__ __launch_bounds__(256) void k4_lstm(const float* __restrict__ w_hh,
                                               float* __restrict__ out,
                                               int write_states) {
    __shared__ float h_s[AG * OO];    // h per agent (2 KB)
    __shared__ float g_s[AG * G4];    // gate pre-activations per agent (8 KB)

    const int tid = threadIdx.x;
    const int o = tid;                // gate output column
    const int ab = blockIdx.x * AG;   // agent base

    u64 w[32];
    const u64* wp = ((const u64*)w_hh) + o * 32;
#pragma unroll
    for (int j = 0; j < 32; j++) w[j] = wp[j];

    for (int e = tid; e < AG * OO; e += 256) h_s[e] = 0.f;

    const int a_u = tid >> 5;   // agent for update phase (warp-uniform)
    const int q = tid & 31;     // float2 chunk within 64 channels
    float2 c2 = make_float2(0.f, 0.f);
    __syncthreads();

    for (int t = 0; t < TT; t++) {
        float gxv[AG];
        const float* gx = g_gates + ((size_t)(t << 11) + ab) * G4 + o;
#pragma unroll
        for (int a = 0; a < AG; a++) gxv[a] = gx[(size_t)a << 8];

        u64 acc[AG];
#pragma unroll
        for (int a = 0; a < AG; a++) acc[a] = 0ull;

        const ulonglong2* hs2 = (const ulonglong2*)h_s;
#pragma unroll
        for (int j = 0; j < 16; j++) {
            u64 w0 = w[2 * j], w1 = w[2 * j + 1];
#pragma unroll
            for (int a = 0; a < AG; a++) {
                ulonglong2 hv = hs2[(a << 4) + j];
                ffma2(acc[a], w0, hv.x);
                ffma2(acc[a], w1, hv.y);
            }
        }
#pragma unroll
        for (int a = 0; a < AG; a++) {
            float2 v = unpack2(acc[a]);
            g_s[(a << 8) + o] = v.x + v.y + gxv[a];
        }
        __syncthreads();

        const float2* gp = (const float2*)(g_s + (a_u << 8));
        float2 gi = gp[q], gf = gp[32 + q], gg = gp[64 + q], go = gp[96 + q];

        c2.x = sigf(gf.x) * c2.x + sigf(gi.x) * tanhf_fast(gg.x);
        c2.y = sigf(gf.y) * c2.y + sigf(gi.y) * tanhf_fast(gg.y);

        float2 h2;
        h2.x = sigf(go.x) * tanhf_fast(c2.x);
        h2.y = sigf(go.y) * tanhf_fast(c2.y);

        ((float2*)h_s)[(a_u << 5) + q] = h2;
        ((float2*)out)[(((size_t)(ab + a_u) * TT + t) << 5) + q] = h2;  // out[n][t][:]
        __syncthreads();
    }

    if (write_states) {
        float2 h2 = ((const float2*)h_s)[(a_u << 5) + q];
        float2* hn = (float2*)(out + (size_t)NN * TT * OO);
        float2* cn = (float2*)(out + (size_t)NN * TT * OO + (size_t)NN * OO);
        hn[((ab + a_u) << 5) + q] = h2;
        cn[((ab + a_u) << 5) + q] = c2;
    }
}

// ---------------------------------------------------------------------------
extern "C" void kernel_launch(void* const* d_in, const int* in_sizes, int n_in,
                              void* d_out, int out_size) {
    const float* x      = (const float*)d_in[0];
    const int*   A      = (const int*)  d_in[1];
    const float* conv_w = (const float*)d_in[2];
    const float* conv_b = (const float*)d_in[3];
    const float* w_ih   = (const float*)d_in[4];
    const float* w_hh   = (const float*)d_in[5];
    const float* b_ih   = (const float*)d_in[6];
    const float* b_hh   = (const float*)d_in[7];
    float* out = (float*)d_out;

    const long main_sz = (long)NN * TT * OO;
    int write_states = (out_size >= main_sz + 2L * NN * OO) ? 1 : 0;

    k1_project<<<(TT * NN) / 8, 256>>>(x, conv_w);
    k23_feat_gates<<<(TT * NN) / 32, 256>>>(A, conv_b, w_ih, b_ih, b_hh);
    k4_lstm<<<NN / AG, 256>>>(w_hh, out, write_states);
}

// round 6
// speedup vs baseline: 1.2389x; 1.2389x over previous
#include <cuda_runtime.h>
#include <cuda_fp16.h>
#include <math.h>

#define NN 2048
#define TT 20
#define KK 32
#define CC 32
#define OO 64
#define G4 256   // 4*OO
#define AG 8     // agents per k4 block

// Scratch (static device globals; no runtime allocation)
__device__ float   g_z[TT * NN * OO];       // z[t][n][o] f32 (center term)
__device__ __half2 g_zh[TT * NN * (OO/2)];  // z fp16 copy (gather/max term)
__device__ float   g_gates[TT * NN * G4];   // gates_x[t][n][0..255]

typedef unsigned long long u64;

__device__ __forceinline__ void ffma2(u64& d, u64 a, u64 b) {
    asm("fma.rn.f32x2 %0, %1, %2, %0;" : "+l"(d) : "l"(a), "l"(b));
}
__device__ __forceinline__ float2 unpack2(u64 v) {
    float2 r;
    asm("mov.b64 {%0,%1}, %2;" : "=f"(r.x), "=f"(r.y) : "l"(v));
    return r;
}
__device__ __forceinline__ u64 pack2(float x, float y) {
    u64 r;
    asm("mov.b64 %0, {%1,%2};" : "=l"(r) : "f"(x), "f"(y));
    return r;
}

// NaN-safe fast sigmoid / tanh (rel err ~1e-7, 2 MUFU each)
__device__ __forceinline__ float sigf(float x) {
    return __fdividef(1.0f, 1.0f + __expf(-x));
}
__device__ __forceinline__ float tanhf_fast(float x) {
    return 1.0f - __fdividef(2.0f, __expf(2.0f * x) + 1.0f);
}

// ---------------------------------------------------------------------------
// K1 (rewritten): z[t][n][o] = sum_c x[n][t][c] * conv_w[o][c]
// 640 blocks x 256 threads; block owns 64 rows. Thread (o = tid&63,
// g = tid>>6) holds conv_w row o in 16 u64 regs and computes z[row][o] for
// 16 rows; x rows staged in smem, read as broadcast LDS.128.
// Writes f32 z (center term) + fp16 z (gather term).
// ---------------------------------------------------------------------------
__global__ __launch_bounds__(256) void k1_project(const float* __restrict__ x,
                                                  const float* __restrict__ conv_w) {
    __shared__ u64 xs[64 * 16];   // 64 rows x 32 floats (8 KB)

    const int tid = threadIdx.x;
    const int o = tid & 63;
    const int g = tid >> 6;             // row group 0..3
    const int row0 = blockIdx.x << 6;   // row = t*N + n

    // conv_w row o -> 16 u64 regs (L2-resident after first wave)
    u64 w[16];
    const u64* wp = ((const u64*)conv_w) + o * 16;
#pragma unroll
    for (int j = 0; j < 16; j++) w[j] = wp[j];

    // stage 64 x-rows: 512 float4, 2 per thread
    {
        const float4* x4 = (const float4*)x;
        float4* xs4 = (float4*)xs;
#pragma unroll
        for (int it = 0; it < 2; it++) {
            int idx = tid + (it << 8);
            int rl = idx >> 3, c4 = idx & 7;
            int row = row0 + rl;
            int t = row >> 11, n = row & (NN - 1);
            xs4[(rl << 3) + c4] = x4[((n * TT + t) << 3) + c4];
        }
    }
    __syncthreads();

    __half* zh = (__half*)g_zh;
#pragma unroll
    for (int rr = 0; rr < 16; rr++) {
        const int rl = (g << 4) + rr;
        const ulonglong2* xr = (const ulonglong2*)(xs + (rl << 4));
        u64 acc = 0ull;
#pragma unroll
        for (int j = 0; j < 8; j++) {
            ulonglong2 xv = xr[j];          // broadcast within warp
            ffma2(acc, w[2 * j], xv.x);
            ffma2(acc, w[2 * j + 1], xv.y);
        }
        float2 v = unpack2(acc);
        float z = v.x + v.y;
        const int row = row0 + rl;
        g_z[(row << 6) + o] = z;
        zh[(row << 6) + o] = __float2half_rn(z);
    }
}

// ---------------------------------------------------------------------------
// K23 (fused gather-max + input GEMM):
// Phase A: block owns 32 rows (t,n); each warp gather-maxes 4 rows (fp16
//          neighbor z, f32 center z + bias) and writes feat to SMEM only.
// Phase B: gates_x[row][o] = feat[row][:] . w_ih[o][:] + bias, 4-row unroll
//          (4 independent f32x2 accumulator chains), broadcast LDS.128 feat.
// ---------------------------------------------------------------------------
__global__ __launch_bounds__(256) void k23_feat_gates(const int* __restrict__ A,
                                                      const float* __restrict__ conv_b,
                                                      const float* __restrict__ w_ih,
                                                      const float* __restrict__ b_ih,
                                                      const float* __restrict__ b_hh) {
    __shared__ u64 fs[32 * 32];  // 32 rows x 32 u64 (64 floats) of feat

    const int tid = threadIdx.x;
    const int lane = tid & 31;
    const int wrp = tid >> 5;
    const int row0 = blockIdx.x << 5;   // first global row (row = t*N + n)

    // ---- preload w_ih row into regs (overlaps phase A) ----
    u64 w[32];
    const u64* wp = ((const u64*)w_ih) + tid * 32;
#pragma unroll
    for (int j = 0; j < 32; j++) w[j] = wp[j];
    const float bias = b_ih[tid] + b_hh[tid];

    const float2 cb = ((const float2*)conv_b)[lane];

    // ---- Phase A: gather-max for this warp's 4 rows ----
#pragma unroll
    for (int rr = 0; rr < 4; rr++) {
        const int row = row0 + (wrp << 2) + rr;
        const int t = row >> 11;
        const int nb = A[(row << 5) + lane];

        __half2 m = __float2half2_rn(-60000.f);
#pragma unroll
        for (int k = 0; k < KK; k++) {
            int r = __shfl_sync(0xffffffffu, nb, k);
            __half2 v = __ldg(&g_zh[(((t << 11) + r) << 5) + lane]);
            m = __hmax2(m, v);
        }
        float2 mf = __half22float2(m);
        float2 zc = ((const float2*)g_z)[(row << 5) + lane];
        fs[((wrp << 2) + rr) * 32 + lane] = pack2(mf.x - zc.x + cb.x,
                                                  mf.y - zc.y + cb.y);
    }
    __syncthreads();

    // ---- Phase B: GEMM, 4 rows per iteration (4 acc chains) ----
    const ulonglong2* fs2 = (const ulonglong2*)fs;
    for (int r = 0; r < 32; r += 4) {
        u64 a0 = 0ull, a1 = 0ull, a2 = 0ull, a3 = 0ull;
#pragma unroll
        for (int j = 0; j < 16; j++) {
            u64 w0 = w[2 * j], w1 = w[2 * j + 1];
            ulonglong2 f0 = fs2[(r + 0) * 16 + j];
            ulonglong2 f1 = fs2[(r + 1) * 16 + j];
            ulonglong2 f2 = fs2[(r + 2) * 16 + j];
            ulonglong2 f3 = fs2[(r + 3) * 16 + j];
            ffma2(a0, w0, f0.x); ffma2(a0, w1, f0.y);
            ffma2(a1, w0, f1.x); ffma2(a1, w1, f1.y);
            ffma2(a2, w0, f2.x); ffma2(a2, w1, f2.y);
            ffma2(a3, w0, f3.x); ffma2(a3, w1, f3.y);
        }
        float2 v0 = unpack2(a0), v1 = unpack2(a1);
        float2 v2 = unpack2(a2), v3 = unpack2(a3);
        g_gates[(size_t)(row0 + r + 0) * G4 + tid] = v0.x + v0.y + bias;
        g_gates[(size_t)(row0 + r + 1) * G4 + tid] = v1.x + v1.y + bias;
        g_gates[(size_t)(row0 + r + 2) * G4 + tid] = v2.x + v2.y + bias;
        g_gates[(size_t)(row0 + r + 3) * G4 + tid] = v3.x + v3.y + bias;
    }
}

// ---------------------------------------------------------------------------
// K4: persistent LSTM. 256 blocks x 256 threads; block owns 8 agents for all
// 20 steps; ~2 blocks/SM. Matvec: thread owns gate col o for all 8 agents,
// w_hh row in 32 u64 regs, h broadcast via LDS.128, packed f32x2 FMA.
// Update: thread owns (agent, 2 channels), c in registers.
// ---------------------------------------------------------------------------
__global__ __launch_bounds__(256) void k4_lstm(const float* __restrict__ w_hh,
                                               float* __restrict__ out,
                                               int write_states) {
    __shared__ float h_s[AG * OO];    // h per agent (2 KB)
    __shared__ float g_s[AG * G4];    // gate pre-activations per agent (8 KB)

    const int tid = threadIdx.x;
    const int o = tid;                // gate output column
    const int ab = blockIdx.x * AG;   // agent base

    u64 w[32];
    const u64* wp = ((const u64*)w_hh) + o * 32;
#pragma unroll
    for (int j = 0; j < 32; j++) w[j] = wp[j];

    for (int e = tid; e < AG * OO; e += 256) h_s[e] = 0.f;

    const int a_u = tid >> 5;   // agent for update phase (warp-uniform)
    const int q = tid & 31;     // float2 chunk within 64 channels
    float2 c2 = make_float2(0.f, 0.f);
    __syncthreads();

    for (int t = 0; t < TT; t++) {
        float gxv[AG];
        const float* gx = g_gates + ((size_t)(t << 11) + ab) * G4 + o;
#pragma unroll
        for (int a = 0; a < AG; a++) gxv[a] = gx[(size_t)a << 8];

        u64 acc[AG];
#pragma unroll
        for (int a = 0; a < AG; a++) acc[a] = 0ull;

        const ulonglong2* hs2 = (const ulonglong2*)h_s;
#pragma unroll
        for (int j = 0; j < 16; j++) {
            u64 w0 = w[2 * j], w1 = w[2 * j + 1];
#pragma unroll
            for (int a = 0; a < AG; a++) {
                ulonglong2 hv = hs2[(a << 4) + j];
                ffma2(acc[a], w0, hv.x);
                ffma2(acc[a], w1, hv.y);
            }
        }
#pragma unroll
        for (int a = 0; a < AG; a++) {
            float2 v = unpack2(acc[a]);
            g_s[(a << 8) + o] = v.x + v.y + gxv[a];
        }
        __syncthreads();

        const float2* gp = (const float2*)(g_s + (a_u << 8));
        float2 gi = gp[q], gf = gp[32 + q], gg = gp[64 + q], go = gp[96 + q];

        c2.x = sigf(gf.x) * c2.x + sigf(gi.x) * tanhf_fast(gg.x);
        c2.y = sigf(gf.y) * c2.y + sigf(gi.y) * tanhf_fast(gg.y);

        float2 h2;
        h2.x = sigf(go.x) * tanhf_fast(c2.x);
        h2.y = sigf(go.y) * tanhf_fast(c2.y);

        ((float2*)h_s)[(a_u << 5) + q] = h2;
        ((float2*)out)[(((size_t)(ab + a_u) * TT + t) << 5) + q] = h2;  // out[n][t][:]
        __syncthreads();
    }

    if (write_states) {
        float2 h2 = ((const float2*)h_s)[(a_u << 5) + q];
        float2* hn = (float2*)(out + (size_t)NN * TT * OO);
        float2* cn = (float2*)(out + (size_t)NN * TT * OO + (size_t)NN * OO);
        hn[((ab + a_u) << 5) + q] = h2;
        cn[((ab + a_u) << 5) + q] = c2;
    }
}

// ---------------------------------------------------------------------------
extern "C" void kernel_launch(void* const* d_in, const int* in_sizes, int n_in,
                              void* d_out, int out_size) {
    const float* x      = (const float*)d_in[0];
    const int*   A      = (const int*)  d_in[1];
    const float* conv_w = (const float*)d_in[2];
    const float* conv_b = (const float*)d_in[3];
    const float* w_ih   = (const float*)d_in[4];
    const float* w_hh   = (const float*)d_in[5];
    const float* b_ih   = (const float*)d_in[6];
    const float* b_hh   = (const float*)d_in[7];
    float* out = (float*)d_out;

    const long main_sz = (long)NN * TT * OO;
    int write_states = (out_size >= main_sz + 2L * NN * OO) ? 1 : 0;

    k1_project<<<(TT * NN) / 64, 256>>>(x, conv_w);
    k23_feat_gates<<<(TT * NN) / 32, 256>>>(A, conv_b, w_ih, b_ih, b_hh);
    k4_lstm<<<NN / AG, 256>>>(w_hh, out, write_states);
}

// round 7
// speedup vs baseline: 1.2476x; 1.0070x over previous
#include <cuda_runtime.h>
#include <cuda_fp16.h>
#include <math.h>

#define NN 2048
#define TT 20
#define KK 32
#define CC 32
#define OO 64
#define G4 256   // 4*OO
#define AG 7     // agents per k4 block (grid 296 = 148 SMs x 2, balanced)
#define K4_GRID 296

// Scratch (static device globals; no runtime allocation)
__device__ float   g_z[TT * NN * OO];       // z[t][n][o] f32 (center term)
__device__ __half2 g_zh[TT * NN * (OO/2)];  // z fp16 copy (gather/max term)
__device__ float   g_gates[TT * NN * G4];   // gates_x[t][n][0..255]

typedef unsigned long long u64;

__device__ __forceinline__ void ffma2(u64& d, u64 a, u64 b) {
    asm("fma.rn.f32x2 %0, %1, %2, %0;" : "+l"(d) : "l"(a), "l"(b));
}
__device__ __forceinline__ float2 unpack2(u64 v) {
    float2 r;
    asm("mov.b64 {%0,%1}, %2;" : "=f"(r.x), "=f"(r.y) : "l"(v));
    return r;
}
__device__ __forceinline__ u64 pack2(float x, float y) {
    u64 r;
    asm("mov.b64 %0, {%1,%2};" : "=l"(r) : "f"(x), "f"(y));
    return r;
}

// NaN-safe fast sigmoid / tanh (rel err ~1e-7, 2 MUFU each)
__device__ __forceinline__ float sigf(float x) {
    return __fdividef(1.0f, 1.0f + __expf(-x));
}
__device__ __forceinline__ float tanhf_fast(float x) {
    return 1.0f - __fdividef(2.0f, __expf(2.0f * x) + 1.0f);
}

// ---------------------------------------------------------------------------
// K1: z[t][n][o] = sum_c x[n][t][c] * conv_w[o][c]
// 640 blocks x 256 threads; block owns 64 rows. Thread (o = tid&63,
// g = tid>>6) holds conv_w row o in 16 u64 regs; computes 16 rows with TWO
// independent f32x2 accumulator chains (halved critical path).
// ---------------------------------------------------------------------------
__global__ __launch_bounds__(256) void k1_project(const float* __restrict__ x,
                                                  const float* __restrict__ conv_w) {
    __shared__ u64 xs[64 * 16];   // 64 rows x 32 floats (8 KB)

    const int tid = threadIdx.x;
    const int o = tid & 63;
    const int g = tid >> 6;             // row group 0..3
    const int row0 = blockIdx.x << 6;   // row = t*N + n

    u64 w[16];
    const u64* wp = ((const u64*)conv_w) + o * 16;
#pragma unroll
    for (int j = 0; j < 16; j++) w[j] = wp[j];

    // stage 64 x-rows: 512 float4, 2 per thread
    {
        const float4* x4 = (const float4*)x;
        float4* xs4 = (float4*)xs;
#pragma unroll
        for (int it = 0; it < 2; it++) {
            int idx = tid + (it << 8);
            int rl = idx >> 3, c4 = idx & 7;
            int row = row0 + rl;
            int t = row >> 11, n = row & (NN - 1);
            xs4[(rl << 3) + c4] = x4[((n * TT + t) << 3) + c4];
        }
    }
    __syncthreads();

    __half* zh = (__half*)g_zh;
#pragma unroll
    for (int rr = 0; rr < 16; rr++) {
        const int rl = (g << 4) + rr;
        const ulonglong2* xr = (const ulonglong2*)(xs + (rl << 4));
        u64 acc0 = 0ull, acc1 = 0ull;     // two independent chains
#pragma unroll
        for (int j = 0; j < 8; j++) {
            ulonglong2 xv = xr[j];          // broadcast within warp
            ffma2(acc0, w[2 * j], xv.x);
            ffma2(acc1, w[2 * j + 1], xv.y);
        }
        float2 v0 = unpack2(acc0), v1 = unpack2(acc1);
        float z = (v0.x + v1.x) + (v0.y + v1.y);
        const int row = row0 + rl;
        g_z[(row << 6) + o] = z;
        zh[(row << 6) + o] = __float2half_rn(z);
    }
}

// ---------------------------------------------------------------------------
// K23 (fused gather-max + input GEMM): unchanged from R5 (attribution).
// ---------------------------------------------------------------------------
__global__ __launch_bounds__(256) void k23_feat_gates(const int* __restrict__ A,
                                                      const float* __restrict__ conv_b,
                                                      const float* __restrict__ w_ih,
                                                      const float* __restrict__ b_ih,
                                                      const float* __restrict__ b_hh) {
    __shared__ u64 fs[32 * 32];  // 32 rows x 32 u64 (64 floats) of feat

    const int tid = threadIdx.x;
    const int lane = tid & 31;
    const int wrp = tid >> 5;
    const int row0 = blockIdx.x << 5;   // first global row (row = t*N + n)

    u64 w[32];
    const u64* wp = ((const u64*)w_ih) + tid * 32;
#pragma unroll
    for (int j = 0; j < 32; j++) w[j] = wp[j];
    const float bias = b_ih[tid] + b_hh[tid];

    const float2 cb = ((const float2*)conv_b)[lane];

#pragma unroll
    for (int rr = 0; rr < 4; rr++) {
        const int row = row0 + (wrp << 2) + rr;
        const int t = row >> 11;
        const int nb = A[(row << 5) + lane];

        __half2 m = __float2half2_rn(-60000.f);
#pragma unroll
        for (int k = 0; k < KK; k++) {
            int r = __shfl_sync(0xffffffffu, nb, k);
            __half2 v = __ldg(&g_zh[(((t << 11) + r) << 5) + lane]);
            m = __hmax2(m, v);
        }
        float2 mf = __half22float2(m);
        float2 zc = ((const float2*)g_z)[(row << 5) + lane];
        fs[((wrp << 2) + rr) * 32 + lane] = pack2(mf.x - zc.x + cb.x,
                                                  mf.y - zc.y + cb.y);
    }
    __syncthreads();

    const ulonglong2* fs2 = (const ulonglong2*)fs;
    for (int r = 0; r < 32; r += 4) {
        u64 a0 = 0ull, a1 = 0ull, a2 = 0ull, a3 = 0ull;
#pragma unroll
        for (int j = 0; j < 16; j++) {
            u64 w0 = w[2 * j], w1 = w[2 * j + 1];
            ulonglong2 f0 = fs2[(r + 0) * 16 + j];
            ulonglong2 f1 = fs2[(r + 1) * 16 + j];
            ulonglong2 f2 = fs2[(r + 2) * 16 + j];
            ulonglong2 f3 = fs2[(r + 3) * 16 + j];
            ffma2(a0, w0, f0.x); ffma2(a0, w1, f0.y);
            ffma2(a1, w0, f1.x); ffma2(a1, w1, f1.y);
            ffma2(a2, w0, f2.x); ffma2(a2, w1, f2.y);
            ffma2(a3, w0, f3.x); ffma2(a3, w1, f3.y);
        }
        float2 v0 = unpack2(a0), v1 = unpack2(a1);
        float2 v2 = unpack2(a2), v3 = unpack2(a3);
        g_gates[(size_t)(row0 + r + 0) * G4 + tid] = v0.x + v0.y + bias;
        g_gates[(size_t)(row0 + r + 1) * G4 + tid] = v1.x + v1.y + bias;
        g_gates[(size_t)(row0 + r + 2) * G4 + tid] = v2.x + v2.y + bias;
        g_gates[(size_t)(row0 + r + 3) * G4 + tid] = v3.x + v3.y + bias;
    }
}

// ---------------------------------------------------------------------------
// K4: persistent LSTM. 296 blocks (=148 SMs x 2, perfectly balanced) x 256
// threads; block owns 7 agents for all 20 steps. Pad slots (agents >= 2048)
// compute clamped duplicates; stores guarded by ownership.
// ---------------------------------------------------------------------------
__global__ __launch_bounds__(256) void k4_lstm(const float* __restrict__ w_hh,
                                               float* __restrict__ out,
                                               int write_states) {
    __shared__ float h_s[AG * OO];    // h per agent
    __shared__ float g_s[AG * G4];    // gate pre-activations per agent

    const int tid = threadIdx.x;
    const int o = tid;                // gate output column
    const int ab = blockIdx.x * AG;   // agent base

    // clamped agent indices for gx loads (pad slots duplicate agent NN-1;
    // their results are never stored)
    int aidx[AG];
#pragma unroll
    for (int a = 0; a < AG; a++) {
        int v = ab + a;
        aidx[a] = (v < NN) ? v : (NN - 1);
    }

    u64 w[32];
    const u64* wp = ((const u64*)w_hh) + o * 32;
#pragma unroll
    for (int j = 0; j < 32; j++) w[j] = wp[j];

    for (int e = tid; e < AG * OO; e += 256) h_s[e] = 0.f;

    const int a_u = tid >> 5;   // agent for update phase (warp-uniform, 0..7)
    const int q = tid & 31;     // float2 chunk within 64 channels
    const bool upd_own = (a_u < AG) && (ab + a_u < NN);
    float2 c2 = make_float2(0.f, 0.f);
    __syncthreads();

    for (int t = 0; t < TT; t++) {
        float gxv[AG];
        const float* gx = g_gates + ((size_t)(t << 11)) * G4 + o;
#pragma unroll
        for (int a = 0; a < AG; a++) gxv[a] = gx[(size_t)aidx[a] << 8];

        u64 acc[AG];
#pragma unroll
        for (int a = 0; a < AG; a++) acc[a] = 0ull;

        const ulonglong2* hs2 = (const ulonglong2*)h_s;
#pragma unroll
        for (int j = 0; j < 16; j++) {
            u64 w0 = w[2 * j], w1 = w[2 * j + 1];
#pragma unroll
            for (int a = 0; a < AG; a++) {
                ulonglong2 hv = hs2[(a << 4) + j];
                ffma2(acc[a], w0, hv.x);
                ffma2(acc[a], w1, hv.y);
            }
        }
#pragma unroll
        for (int a = 0; a < AG; a++) {
            float2 v = unpack2(acc[a]);
            g_s[(a << 8) + o] = v.x + v.y + gxv[a];
        }
        __syncthreads();

        if (a_u < AG) {
            const float2* gp = (const float2*)(g_s + (a_u << 8));
            float2 gi = gp[q], gf = gp[32 + q], gg = gp[64 + q], go = gp[96 + q];

            c2.x = sigf(gf.x) * c2.x + sigf(gi.x) * tanhf_fast(gg.x);
            c2.y = sigf(gf.y) * c2.y + sigf(gi.y) * tanhf_fast(gg.y);

            float2 h2;
            h2.x = sigf(go.x) * tanhf_fast(c2.x);
            h2.y = sigf(go.y) * tanhf_fast(c2.y);

            ((float2*)h_s)[(a_u << 5) + q] = h2;
            if (upd_own)
                ((float2*)out)[(((size_t)(ab + a_u) * TT + t) << 5) + q] = h2;
        }
        __syncthreads();
    }

    if (write_states && upd_own) {
        float2 h2 = ((const float2*)h_s)[(a_u << 5) + q];
        float2* hn = (float2*)(out + (size_t)NN * TT * OO);
        float2* cn = (float2*)(out + (size_t)NN * TT * OO + (size_t)NN * OO);
        hn[((ab + a_u) << 5) + q] = h2;
        cn[((ab + a_u) << 5) + q] = c2;
    }
}

// ---------------------------------------------------------------------------
extern "C" void kernel_launch(void* const* d_in, const int* in_sizes, int n_in,
                              void* d_out, int out_size) {
    const float* x      = (const float*)d_in[0];
    const int*   A      = (const int*)  d_in[1];
    const float* conv_w = (const float*)d_in[2];
    const float* conv_b = (const float*)d_in[3];
    const float* w_ih   = (const float*)d_in[4];
    const float* w_hh   = (const float*)d_in[5];
    const float* b_ih   = (const float*)d_in[6];
    const float* b_hh   = (const float*)d_in[7];
    float* out = (float*)d_out;

    const long main_sz = (long)NN * TT * OO;
    int write_states = (out_size >= main_sz + 2L * NN * OO) ? 1 : 0;

    k1_project<<<(TT * NN) / 64, 256>>>(x, conv_w);
    k23_feat_gates<<<(TT * NN) / 32, 256>>>(A, conv_b, w_ih, b_ih, b_hh);
    k4_lstm<<<K4_GRID, 256>>>(w_hh, out, write_states);
}

// round 8
// speedup vs baseline: 1.5902x; 1.2746x over previous
#include <cuda_runtime.h>
#include <cuda_fp16.h>
#include <math.h>

#define NN 2048
#define TT 20
#define KK 32
#define CC 32
#define OO 64
#define G4 256   // 4*OO

// Scratch (static device globals; no runtime allocation)
__device__ float   g_z[TT * NN * OO];       // z[t][n][o] f32 (center term)
__device__ __half2 g_zh[TT * NN * (OO/2)];  // z fp16 copy (gather/max term)
__device__ float   g_gates[TT * NN * G4];   // gates_x[t][n][0..255]

typedef unsigned long long u64;

__device__ __forceinline__ void ffma2(u64& d, u64 a, u64 b) {
    asm("fma.rn.f32x2 %0, %1, %2, %0;" : "+l"(d) : "l"(a), "l"(b));
}
__device__ __forceinline__ float2 unpack2(u64 v) {
    float2 r;
    asm("mov.b64 {%0,%1}, %2;" : "=f"(r.x), "=f"(r.y) : "l"(v));
    return r;
}
__device__ __forceinline__ u64 pack2(float x, float y) {
    u64 r;
    asm("mov.b64 %0, {%1,%2};" : "=l"(r) : "f"(x), "f"(y));
    return r;
}

// NaN-safe fast sigmoid / tanh (rel err ~1e-7, 2 MUFU each)
__device__ __forceinline__ float sigf(float x) {
    return __fdividef(1.0f, 1.0f + __expf(-x));
}
__device__ __forceinline__ float tanhf_fast(float x) {
    return 1.0f - __fdividef(2.0f, __expf(2.0f * x) + 1.0f);
}

// ---------------------------------------------------------------------------
// K1: z[t][n][o] = sum_c x[n][t][c] * conv_w[o][c]  (R5 form, reverted)
// ---------------------------------------------------------------------------
__global__ __launch_bounds__(256) void k1_project(const float* __restrict__ x,
                                                  const float* __restrict__ conv_w) {
    __shared__ u64 xs[64 * 16];   // 64 rows x 32 floats (8 KB)

    const int tid = threadIdx.x;
    const int o = tid & 63;
    const int g = tid >> 6;             // row group 0..3
    const int row0 = blockIdx.x << 6;   // row = t*N + n

    u64 w[16];
    const u64* wp = ((const u64*)conv_w) + o * 16;
#pragma unroll
    for (int j = 0; j < 16; j++) w[j] = wp[j];

    {
        const float4* x4 = (const float4*)x;
        float4* xs4 = (float4*)xs;
#pragma unroll
        for (int it = 0; it < 2; it++) {
            int idx = tid + (it << 8);
            int rl = idx >> 3, c4 = idx & 7;
            int row = row0 + rl;
            int t = row >> 11, n = row & (NN - 1);
            xs4[(rl << 3) + c4] = x4[((n * TT + t) << 3) + c4];
        }
    }
    __syncthreads();

    __half* zh = (__half*)g_zh;
#pragma unroll
    for (int rr = 0; rr < 16; rr++) {
        const int rl = (g << 4) + rr;
        const ulonglong2* xr = (const ulonglong2*)(xs + (rl << 4));
        u64 acc = 0ull;
#pragma unroll
        for (int j = 0; j < 8; j++) {
            ulonglong2 xv = xr[j];
            ffma2(acc, w[2 * j], xv.x);
            ffma2(acc, w[2 * j + 1], xv.y);
        }
        float2 v = unpack2(acc);
        float z = v.x + v.y;
        const int row = row0 + rl;
        g_z[(row << 6) + o] = z;
        zh[(row << 6) + o] = __float2half_rn(z);
    }
}

// ---------------------------------------------------------------------------
// K23 (fused gather-max + input GEMM): unchanged (attribution).
// ---------------------------------------------------------------------------
__global__ __launch_bounds__(256) void k23_feat_gates(const int* __restrict__ A,
                                                      const float* __restrict__ conv_b,
                                                      const float* __restrict__ w_ih,
                                                      const float* __restrict__ b_ih,
                                                      const float* __restrict__ b_hh) {
    __shared__ u64 fs[32 * 32];

    const int tid = threadIdx.x;
    const int lane = tid & 31;
    const int wrp = tid >> 5;
    const int row0 = blockIdx.x << 5;

    u64 w[32];
    const u64* wp = ((const u64*)w_ih) + tid * 32;
#pragma unroll
    for (int j = 0; j < 32; j++) w[j] = wp[j];
    const float bias = b_ih[tid] + b_hh[tid];

    const float2 cb = ((const float2*)conv_b)[lane];

#pragma unroll
    for (int rr = 0; rr < 4; rr++) {
        const int row = row0 + (wrp << 2) + rr;
        const int t = row >> 11;
        const int nb = A[(row << 5) + lane];

        __half2 m = __float2half2_rn(-60000.f);
#pragma unroll
        for (int k = 0; k < KK; k++) {
            int r = __shfl_sync(0xffffffffu, nb, k);
            __half2 v = __ldg(&g_zh[(((t << 11) + r) << 5) + lane]);
            m = __hmax2(m, v);
        }
        float2 mf = __half22float2(m);
        float2 zc = ((const float2*)g_z)[(row << 5) + lane];
        fs[((wrp << 2) + rr) * 32 + lane] = pack2(mf.x - zc.x + cb.x,
                                                  mf.y - zc.y + cb.y);
    }
    __syncthreads();

    const ulonglong2* fs2 = (const ulonglong2*)fs;
    for (int r = 0; r < 32; r += 4) {
        u64 a0 = 0ull, a1 = 0ull, a2 = 0ull, a3 = 0ull;
#pragma unroll
        for (int j = 0; j < 16; j++) {
            u64 w0 = w[2 * j], w1 = w[2 * j + 1];
            ulonglong2 f0 = fs2[(r + 0) * 16 + j];
            ulonglong2 f1 = fs2[(r + 1) * 16 + j];
            ulonglong2 f2 = fs2[(r + 2) * 16 + j];
            ulonglong2 f3 = fs2[(r + 3) * 16 + j];
            ffma2(a0, w0, f0.x); ffma2(a0, w1, f0.y);
            ffma2(a1, w0, f1.x); ffma2(a1, w1, f1.y);
            ffma2(a2, w0, f2.x); ffma2(a2, w1, f2.y);
            ffma2(a3, w0, f3.x); ffma2(a3, w1, f3.y);
        }
        float2 v0 = unpack2(a0), v1 = unpack2(a1);
        float2 v2 = unpack2(a2), v3 = unpack2(a3);
        g_gates[(size_t)(row0 + r + 0) * G4 + tid] = v0.x + v0.y + bias;
        g_gates[(size_t)(row0 + r + 1) * G4 + tid] = v1.x + v1.y + bias;
        g_gates[(size_t)(row0 + r + 2) * G4 + tid] = v2.x + v2.y + bias;
        g_gates[(size_t)(row0 + r + 3) * G4 + tid] = v3.x + v3.y + bias;
    }
}

// ---------------------------------------------------------------------------
// K4: tensor-core LSTM. 128 blocks x 256 threads; block owns 16 agents.
// Matvec per step: h[16x64] (fp16, smem) x w_hh^T[64x256] (fp16 B-fragments
// in registers) -> g_s[16x256] f32 via mma.sync.m16n8k16; each warp owns a
// 32-column slice (4 n-tiles x 4 k-steps). Update: thread (agent, 4 chans),
// c in f32 registers, gx added from global (prefetched at step top).
// h stride 68 halves / g_s stride 260 floats for conflict-free smem.
// ---------------------------------------------------------------------------
__global__ __launch_bounds__(256) void k4_lstm(const float* __restrict__ w_hh,
                                               float* __restrict__ out,
                                               int write_states) {
    __shared__ __half hs[16 * 68];   // h fp16, padded rows
    __shared__ float  g_s[16 * 260]; // recurrent gate pre-acts, padded rows

    const int tid = threadIdx.x;
    const int wid = tid >> 5;
    const int lane = tid & 31;
    const int gid = lane >> 2;      // 0..7
    const int tig = lane & 3;       // 0..3
    const int ab = blockIdx.x << 4; // agent base (16 per block)
    const int nbase = wid << 5;     // warp's 32 output columns

    // ---- B fragments: b[nt][ks][2], w_hh row n0 (fp32 -> fp16 once) ----
    unsigned b[4][4][2];
#pragma unroll
    for (int nt = 0; nt < 4; nt++) {
        const int n0 = nbase + (nt << 3) + gid;
        const float* wr = w_hh + n0 * 64;
#pragma unroll
        for (int ks = 0; ks < 4; ks++) {
            const int k0 = (ks << 4) + (tig << 1);
            float2 lo = *(const float2*)(wr + k0);
            float2 hi = *(const float2*)(wr + k0 + 8);
            __half2 p0 = __floats2half2_rn(lo.x, lo.y);
            __half2 p1 = __floats2half2_rn(hi.x, hi.y);
            b[nt][ks][0] = *(unsigned*)&p0;
            b[nt][ks][1] = *(unsigned*)&p1;
        }
    }

    for (int e = tid; e < 16 * 68; e += 256) hs[e] = __float2half(0.f);

    // update-phase mapping: thread -> (agent a_u, channels 4q..4q+3)
    const int a_u = tid >> 4;   // 0..15
    const int q = tid & 15;     // 0..15
    float4 c4 = make_float4(0.f, 0.f, 0.f, 0.f);
    float4 h_last = make_float4(0.f, 0.f, 0.f, 0.f);
    __syncthreads();

    for (int t = 0; t < TT; t++) {
        // ---- prefetch this step's gx for the update phase (hides L2 lat) ----
        const float* gx = g_gates + (((size_t)(t << 11) + ab + a_u) << 8) + (q << 2);
        float4 xi = *(const float4*)(gx);
        float4 xf = *(const float4*)(gx + 64);
        float4 xg = *(const float4*)(gx + 128);
        float4 xo = *(const float4*)(gx + 192);

        // ---- A fragments from hs ----
        unsigned a[4][4];
#pragma unroll
        for (int ks = 0; ks < 4; ks++) {
            const int col = (ks << 4) + (tig << 1);
            a[ks][0] = *(const unsigned*)(hs + gid * 68 + col);
            a[ks][1] = *(const unsigned*)(hs + (gid + 8) * 68 + col);
            a[ks][2] = *(const unsigned*)(hs + gid * 68 + col + 8);
            a[ks][3] = *(const unsigned*)(hs + (gid + 8) * 68 + col + 8);
        }

        // ---- MMA: 4 n-tiles x 4 k-steps ----
#pragma unroll
        for (int nt = 0; nt < 4; nt++) {
            float c0 = 0.f, c1 = 0.f, c2 = 0.f, c3 = 0.f;
#pragma unroll
            for (int ks = 0; ks < 4; ks++) {
                asm volatile(
                    "mma.sync.aligned.m16n8k16.row.col.f32.f16.f16.f32 "
                    "{%0,%1,%2,%3}, {%4,%5,%6,%7}, {%8,%9}, {%0,%1,%2,%3};"
                    : "+f"(c0), "+f"(c1), "+f"(c2), "+f"(c3)
                    : "r"(a[ks][0]), "r"(a[ks][1]), "r"(a[ks][2]), "r"(a[ks][3]),
                      "r"(b[nt][ks][0]), "r"(b[nt][ks][1]));
            }
            const int col = nbase + (nt << 3) + (tig << 1);
            g_s[gid * 260 + col] = c0;
            g_s[gid * 260 + col + 1] = c1;
            g_s[(gid + 8) * 260 + col] = c2;
            g_s[(gid + 8) * 260 + col + 1] = c3;
        }
        __syncthreads();

        // ---- nonlinear update (gates i, f, g, o) ----
        const float* gr = g_s + a_u * 260 + (q << 2);
        float4 gi = *(const float4*)(gr);
        float4 gf = *(const float4*)(gr + 64);
        float4 gg = *(const float4*)(gr + 128);
        float4 go = *(const float4*)(gr + 192);
        gi.x += xi.x; gi.y += xi.y; gi.z += xi.z; gi.w += xi.w;
        gf.x += xf.x; gf.y += xf.y; gf.z += xf.z; gf.w += xf.w;
        gg.x += xg.x; gg.y += xg.y; gg.z += xg.z; gg.w += xg.w;
        go.x += xo.x; go.y += xo.y; go.z += xo.z; go.w += xo.w;

        c4.x = sigf(gf.x) * c4.x + sigf(gi.x) * tanhf_fast(gg.x);
        c4.y = sigf(gf.y) * c4.y + sigf(gi.y) * tanhf_fast(gg.y);
        c4.z = sigf(gf.z) * c4.z + sigf(gi.z) * tanhf_fast(gg.z);
        c4.w = sigf(gf.w) * c4.w + sigf(gi.w) * tanhf_fast(gg.w);

        float4 h4;
        h4.x = sigf(go.x) * tanhf_fast(c4.x);
        h4.y = sigf(go.y) * tanhf_fast(c4.y);
        h4.z = sigf(go.z) * tanhf_fast(c4.z);
        h4.w = sigf(go.w) * tanhf_fast(c4.w);
        h_last = h4;

        *(__half2*)(hs + a_u * 68 + (q << 2))     = __floats2half2_rn(h4.x, h4.y);
        *(__half2*)(hs + a_u * 68 + (q << 2) + 2) = __floats2half2_rn(h4.z, h4.w);
        *(float4*)(out + (((size_t)(ab + a_u) * TT + t) << 6) + (q << 2)) = h4;
        __syncthreads();
    }

    if (write_states) {
        float4* hn = (float4*)(out + (size_t)NN * TT * OO);
        float4* cn = (float4*)(out + (size_t)NN * TT * OO + (size_t)NN * OO);
        hn[((ab + a_u) << 4) + q] = h_last;
        cn[((ab + a_u) << 4) + q] = c4;
    }
}

// ---------------------------------------------------------------------------
extern "C" void kernel_launch(void* const* d_in, const int* in_sizes, int n_in,
                              void* d_out, int out_size) {
    const float* x      = (const float*)d_in[0];
    const int*   A      = (const int*)  d_in[1];
    const float* conv_w = (const float*)d_in[2];
    const float* conv_b = (const float*)d_in[3];
    const float* w_ih   = (const float*)d_in[4];
    const float* w_hh   = (const float*)d_in[5];
    const float* b_ih   = (const float*)d_in[6];
    const float* b_hh   = (const float*)d_in[7];
    float* out = (float*)d_out;

    const long main_sz = (long)NN * TT * OO;
    int write_states = (out_size >= main_sz + 2L * NN * OO) ? 1 : 0;

    k1_project<<<(TT * NN) / 64, 256>>>(x, conv_w);
    k23_feat_gates<<<(TT * NN) / 32, 256>>>(A, conv_b, w_ih, b_ih, b_hh);
    k4_lstm<<<NN / 16, 256>>>(w_hh, out, write_states);
}

// round 9
// speedup vs baseline: 2.9047x; 1.8266x over previous
#include <cuda_runtime.h>
#include <cuda_fp16.h>
#include <math.h>

#define NN 2048
#define TT 20
#define KK 32
#define CC 32
#define OO 64
#define G4 256   // 4*OO

// Scratch (static device globals; no runtime allocation)
__device__ float   g_z[TT * NN * OO];       // z[t][n][o] f32 (center term)
__device__ __half2 g_zh[TT * NN * (OO/2)];  // z fp16 copy (gather/max term)
__device__ float   g_gates[TT * NN * G4];   // gates_x[t][n][0..255]

typedef unsigned long long u64;

__device__ __forceinline__ void ffma2(u64& d, u64 a, u64 b) {
    asm("fma.rn.f32x2 %0, %1, %2, %0;" : "+l"(d) : "l"(a), "l"(b));
}
__device__ __forceinline__ float2 unpack2(u64 v) {
    float2 r;
    asm("mov.b64 {%0,%1}, %2;" : "=f"(r.x), "=f"(r.y) : "l"(v));
    return r;
}

// NaN-safe fast sigmoid / tanh (rel err ~1e-7, 2 MUFU each)
__device__ __forceinline__ float sigf(float x) {
    return __fdividef(1.0f, 1.0f + __expf(-x));
}
__device__ __forceinline__ float tanhf_fast(float x) {
    return 1.0f - __fdividef(2.0f, __expf(2.0f * x) + 1.0f);
}

// ---------------------------------------------------------------------------
// K1: z[t][n][o] = sum_c x[n][t][c] * conv_w[o][c]
// Row-pair interleaved accumulator chains (2x ILP, identical load pattern).
// ---------------------------------------------------------------------------
__global__ __launch_bounds__(256) void k1_project(const float* __restrict__ x,
                                                  const float* __restrict__ conv_w) {
    __shared__ u64 xs[64 * 16];   // 64 rows x 32 floats (8 KB)

    const int tid = threadIdx.x;
    const int o = tid & 63;
    const int g = tid >> 6;             // row group 0..3
    const int row0 = blockIdx.x << 6;   // row = t*N + n

    u64 w[16];
    const u64* wp = ((const u64*)conv_w) + o * 16;
#pragma unroll
    for (int j = 0; j < 16; j++) w[j] = wp[j];

    {
        const float4* x4 = (const float4*)x;
        float4* xs4 = (float4*)xs;
#pragma unroll
        for (int it = 0; it < 2; it++) {
            int idx = tid + (it << 8);
            int rl = idx >> 3, c4 = idx & 7;
            int row = row0 + rl;
            int t = row >> 11, n = row & (NN - 1);
            xs4[(rl << 3) + c4] = x4[((n * TT + t) << 3) + c4];
        }
    }
    __syncthreads();

    __half* zh = (__half*)g_zh;
#pragma unroll
    for (int rp = 0; rp < 8; rp++) {
        const int rl0 = (g << 4) + (rp << 1);
        const ulonglong2* xr0 = (const ulonglong2*)(xs + (rl0 << 4));
        const ulonglong2* xr1 = (const ulonglong2*)(xs + ((rl0 + 1) << 4));
        u64 accA = 0ull, accB = 0ull;   // two independent row chains
#pragma unroll
        for (int j = 0; j < 8; j++) {
            ulonglong2 xa = xr0[j];
            ulonglong2 xb = xr1[j];
            ffma2(accA, w[2 * j], xa.x);
            ffma2(accB, w[2 * j], xb.x);
            ffma2(accA, w[2 * j + 1], xa.y);
            ffma2(accB, w[2 * j + 1], xb.y);
        }
        float2 va = unpack2(accA), vb = unpack2(accB);
        float za = va.x + va.y, zb = vb.x + vb.y;
        const int rowA = row0 + rl0;
        g_z[(rowA << 6) + o] = za;
        g_z[((rowA + 1) << 6) + o] = zb;
        zh[(rowA << 6) + o] = __float2half_rn(za);
        zh[((rowA + 1) << 6) + o] = __float2half_rn(zb);
    }
}

// ---------------------------------------------------------------------------
// K23 (fused gather-max + tensor-core input GEMM):
// Phase A: block owns 32 rows; each warp gather-maxes 4 rows (fp16 neighbor
//          z, f32 center z + bias) and writes feat as fp16 to smem
//          (stride 72 halves -> conflict-free fragment loads).
// Phase B: gates_x[32x256] = feat[32x64] @ w_ih^T via mma.sync.m16n8k16;
//          warp owns a 32-col slice (2 m-tiles x 4 n-tiles x 4 k-steps),
//          f32 accum, bias epilogue, direct float2 stores.
// ---------------------------------------------------------------------------
__global__ __launch_bounds__(256) void k23_feat_gates(const int* __restrict__ A,
                                                      const float* __restrict__ conv_b,
                                                      const float* __restrict__ w_ih,
                                                      const float* __restrict__ b_ih,
                                                      const float* __restrict__ b_hh) {
    __shared__ __half fs[32 * 72];   // feat fp16, padded stride (4.5 KB)

    const int tid = threadIdx.x;
    const int lane = tid & 31;
    const int wrp = tid >> 5;
    const int gid = lane >> 2;       // 0..7
    const int tig = lane & 3;        // 0..3
    const int row0 = blockIdx.x << 5;
    const int nbase = wrp << 5;      // warp's 32 gate columns

    // ---- B fragments from w_ih (fp32 -> fp16 once) + bias ----
    unsigned b[4][4][2];
    float2 biasv[4];
#pragma unroll
    for (int nt = 0; nt < 4; nt++) {
        const int n0 = nbase + (nt << 3) + gid;
        const float* wr = w_ih + n0 * 64;
#pragma unroll
        for (int ks = 0; ks < 4; ks++) {
            const int k0 = (ks << 4) + (tig << 1);
            float2 lo = *(const float2*)(wr + k0);
            float2 hi = *(const float2*)(wr + k0 + 8);
            __half2 p0 = __floats2half2_rn(lo.x, lo.y);
            __half2 p1 = __floats2half2_rn(hi.x, hi.y);
            b[nt][ks][0] = *(unsigned*)&p0;
            b[nt][ks][1] = *(unsigned*)&p1;
        }
        const int col = nbase + (nt << 3) + (tig << 1);
        biasv[nt].x = b_ih[col] + b_hh[col];
        biasv[nt].y = b_ih[col + 1] + b_hh[col + 1];
    }

    const float2 cb = ((const float2*)conv_b)[lane];

    // ---- Phase A: gather-max for this warp's 4 rows, feat -> fp16 smem ----
#pragma unroll
    for (int rr = 0; rr < 4; rr++) {
        const int row = row0 + (wrp << 2) + rr;
        const int t = row >> 11;
        const int nb = A[(row << 5) + lane];

        __half2 m = __float2half2_rn(-60000.f);
#pragma unroll
        for (int k = 0; k < KK; k++) {
            int r = __shfl_sync(0xffffffffu, nb, k);
            __half2 v = __ldg(&g_zh[(((t << 11) + r) << 5) + lane]);
            m = __hmax2(m, v);
        }
        float2 mf = __half22float2(m);
        float2 zc = ((const float2*)g_z)[(row << 5) + lane];
        *(__half2*)(fs + ((wrp << 2) + rr) * 72 + (lane << 1)) =
            __floats2half2_rn(mf.x - zc.x + cb.x, mf.y - zc.y + cb.y);
    }
    __syncthreads();

    // ---- Phase B: MMA ----
#pragma unroll
    for (int mt = 0; mt < 2; mt++) {
        const int rb = mt << 4;
        unsigned a[4][4];
#pragma unroll
        for (int ks = 0; ks < 4; ks++) {
            const int col = (ks << 4) + (tig << 1);
            a[ks][0] = *(const unsigned*)(fs + (rb + gid) * 72 + col);
            a[ks][1] = *(const unsigned*)(fs + (rb + gid + 8) * 72 + col);
            a[ks][2] = *(const unsigned*)(fs + (rb + gid) * 72 + col + 8);
            a[ks][3] = *(const unsigned*)(fs + (rb + gid + 8) * 72 + col + 8);
        }
#pragma unroll
        for (int nt = 0; nt < 4; nt++) {
            float c0 = 0.f, c1 = 0.f, c2 = 0.f, c3 = 0.f;
#pragma unroll
            for (int ks = 0; ks < 4; ks++) {
                asm volatile(
                    "mma.sync.aligned.m16n8k16.row.col.f32.f16.f16.f32 "
                    "{%0,%1,%2,%3}, {%4,%5,%6,%7}, {%8,%9}, {%0,%1,%2,%3};"
                    : "+f"(c0), "+f"(c1), "+f"(c2), "+f"(c3)
                    : "r"(a[ks][0]), "r"(a[ks][1]), "r"(a[ks][2]), "r"(a[ks][3]),
                      "r"(b[nt][ks][0]), "r"(b[nt][ks][1]));
            }
            const int col = nbase + (nt << 3) + (tig << 1);
            const int rowA = row0 + rb + gid;
            float2 lo = make_float2(c0 + biasv[nt].x, c1 + biasv[nt].y);
            float2 hi = make_float2(c2 + biasv[nt].x, c3 + biasv[nt].y);
            *(float2*)(g_gates + (size_t)rowA * G4 + col) = lo;
            *(float2*)(g_gates + (size_t)(rowA + 8) * G4 + col) = hi;
        }
    }
}

// ---------------------------------------------------------------------------
// K4: tensor-core LSTM (unchanged from R7). 128 blocks x 256 threads; block
// owns 16 agents; mma.sync recurrence, f32 update, c in registers.
// ---------------------------------------------------------------------------
__global__ __launch_bounds__(256) void k4_lstm(const float* __restrict__ w_hh,
                                               float* __restrict__ out,
                                               int write_states) {
    __shared__ __half hs[16 * 68];   // h fp16, padded rows
    __shared__ float  g_s[16 * 260]; // recurrent gate pre-acts, padded rows

    const int tid = threadIdx.x;
    const int wid = tid >> 5;
    const int lane = tid & 31;
    const int gid = lane >> 2;      // 0..7
    const int tig = lane & 3;       // 0..3
    const int ab = blockIdx.x << 4; // agent base (16 per block)
    const int nbase = wid << 5;     // warp's 32 output columns

    unsigned b[4][4][2];
#pragma unroll
    for (int nt = 0; nt < 4; nt++) {
        const int n0 = nbase + (nt << 3) + gid;
        const float* wr = w_hh + n0 * 64;
#pragma unroll
        for (int ks = 0; ks < 4; ks++) {
            const int k0 = (ks << 4) + (tig << 1);
            float2 lo = *(const float2*)(wr + k0);
            float2 hi = *(const float2*)(wr + k0 + 8);
            __half2 p0 = __floats2half2_rn(lo.x, lo.y);
            __half2 p1 = __floats2half2_rn(hi.x, hi.y);
            b[nt][ks][0] = *(unsigned*)&p0;
            b[nt][ks][1] = *(unsigned*)&p1;
        }
    }

    for (int e = tid; e < 16 * 68; e += 256) hs[e] = __float2half(0.f);

    const int a_u = tid >> 4;   // 0..15
    const int q = tid & 15;     // 0..15
    float4 c4 = make_float4(0.f, 0.f, 0.f, 0.f);
    float4 h_last = make_float4(0.f, 0.f, 0.f, 0.f);
    __syncthreads();

    for (int t = 0; t < TT; t++) {
        const float* gx = g_gates + (((size_t)(t << 11) + ab + a_u) << 8) + (q << 2);
        float4 xi = *(const float4*)(gx);
        float4 xf = *(const float4*)(gx + 64);
        float4 xg = *(const float4*)(gx + 128);
        float4 xo = *(const float4*)(gx + 192);

        unsigned a[4][4];
#pragma unroll
        for (int ks = 0; ks < 4; ks++) {
            const int col = (ks << 4) + (tig << 1);
            a[ks][0] = *(const unsigned*)(hs + gid * 68 + col);
            a[ks][1] = *(const unsigned*)(hs + (gid + 8) * 68 + col);
            a[ks][2] = *(const unsigned*)(hs + gid * 68 + col + 8);
            a[ks][3] = *(const unsigned*)(hs + (gid + 8) * 68 + col + 8);
        }

#pragma unroll
        for (int nt = 0; nt < 4; nt++) {
            float c0 = 0.f, c1 = 0.f, c2 = 0.f, c3 = 0.f;
#pragma unroll
            for (int ks = 0; ks < 4; ks++) {
                asm volatile(
                    "mma.sync.aligned.m16n8k16.row.col.f32.f16.f16.f32 "
                    "{%0,%1,%2,%3}, {%4,%5,%6,%7}, {%8,%9}, {%0,%1,%2,%3};"
                    : "+f"(c0), "+f"(c1), "+f"(c2), "+f"(c3)
                    : "r"(a[ks][0]), "r"(a[ks][1]), "r"(a[ks][2]), "r"(a[ks][3]),
                      "r"(b[nt][ks][0]), "r"(b[nt][ks][1]));
            }
            const int col = nbase + (nt << 3) + (tig << 1);
            g_s[gid * 260 + col] = c0;
            g_s[gid * 260 + col + 1] = c1;
            g_s[(gid + 8) * 260 + col] = c2;
            g_s[(gid + 8) * 260 + col + 1] = c3;
        }
        __syncthreads();

        const float* gr = g_s + a_u * 260 + (q << 2);
        float4 gi = *(const float4*)(gr);
        float4 gf = *(const float4*)(gr + 64);
        float4 gg = *(const float4*)(gr + 128);
        float4 go = *(const float4*)(gr + 192);
        gi.x += xi.x; gi.y += xi.y; gi.z += xi.z; gi.w += xi.w;
        gf.x += xf.x; gf.y += xf.y; gf.z += xf.z; gf.w += xf.w;
        gg.x += xg.x; gg.y += xg.y; gg.z += xg.z; gg.w += xg.w;
        go.x += xo.x; go.y += xo.y; go.z += xo.z; go.w += xo.w;

        c4.x = sigf(gf.x) * c4.x + sigf(gi.x) * tanhf_fast(gg.x);
        c4.y = sigf(gf.y) * c4.y + sigf(gi.y) * tanhf_fast(gg.y);
        c4.z = sigf(gf.z) * c4.z + sigf(gi.z) * tanhf_fast(gg.z);
        c4.w = sigf(gf.w) * c4.w + sigf(gi.w) * tanhf_fast(gg.w);

        float4 h4;
        h4.x = sigf(go.x) * tanhf_fast(c4.x);
        h4.y = sigf(go.y) * tanhf_fast(c4.y);
        h4.z = sigf(go.z) * tanhf_fast(c4.z);
        h4.w = sigf(go.w) * tanhf_fast(c4.w);
        h_last = h4;

        *(__half2*)(hs + a_u * 68 + (q << 2))     = __floats2half2_rn(h4.x, h4.y);
        *(__half2*)(hs + a_u * 68 + (q << 2) + 2) = __floats2half2_rn(h4.z, h4.w);
        *(float4*)(out + (((size_t)(ab + a_u) * TT + t) << 6) + (q << 2)) = h4;
        __syncthreads();
    }

    if (write_states) {
        float4* hn = (float4*)(out + (size_t)NN * TT * OO);
        float4* cn = (float4*)(out + (size_t)NN * TT * OO + (size_t)NN * OO);
        hn[((ab + a_u) << 4) + q] = h_last;
        cn[((ab + a_u) << 4) + q] = c4;
    }
}

// ---------------------------------------------------------------------------
extern "C" void kernel_launch(void* const* d_in, const int* in_sizes, int n_in,
                              void* d_out, int out_size) {
    const float* x      = (const float*)d_in[0];
    const int*   A      = (const int*)  d_in[1];
    const float* conv_w = (const float*)d_in[2];
    const float* conv_b = (const float*)d_in[3];
    const float* w_ih   = (const float*)d_in[4];
    const float* w_hh   = (const float*)d_in[5];
    const float* b_ih   = (const float*)d_in[6];
    const float* b_hh   = (const float*)d_in[7];
    float* out = (float*)d_out;

    const long main_sz = (long)NN * TT * OO;
    int write_states = (out_size >= main_sz + 2L * NN * OO) ? 1 : 0;

    k1_project<<<(TT * NN) / 64, 256>>>(x, conv_w);
    k23_feat_gates<<<(TT * NN) / 32, 256>>>(A, conv_b, w_ih, b_ih, b_hh);
    k4_lstm<<<NN / 16, 256>>>(w_hh, out, write_states);
}

// round 10
// speedup vs baseline: 3.1750x; 1.0931x over previous
#include <cuda_runtime.h>
#include <cuda_fp16.h>
#include <math.h>

#define NN 2048
#define TT 20
#define KK 32
#define CC 32
#define OO 64
#define G4 256   // 4*OO

// Scratch (static device globals; no runtime allocation)
__device__ float   g_z[TT * NN * OO];       // z[t][n][o] f32 (center term)
__device__ __half2 g_zh[TT * NN * (OO/2)];  // z fp16 copy (gather/max term)
__device__ float   g_gates[TT * NN * G4];   // gates_x[t][n][0..255]

// NaN-safe fast sigmoid / tanh (rel err ~1e-7, 2 MUFU each)
__device__ __forceinline__ float sigf(float x) {
    return __fdividef(1.0f, 1.0f + __expf(-x));
}
__device__ __forceinline__ float tanhf_fast(float x) {
    return 1.0f - __fdividef(2.0f, __expf(2.0f * x) + 1.0f);
}

// ---------------------------------------------------------------------------
// K1 (tensor-core): z[rows x 64] = x[rows x 32] @ conv_w^T[32 x 64]
// 320 blocks x 256 threads; block owns 128 rows. x converted to fp16 in smem
// (stride 40 halves -> conflict-free fragments); conv_w as fp16 B-fragments;
// f32 accumulate; z stored f32 (center term) + fp16 (gather term).
// ---------------------------------------------------------------------------
__global__ __launch_bounds__(256) void k1_project(const float* __restrict__ x,
                                                  const float* __restrict__ conv_w) {
    __shared__ __half xs[128 * 40];   // 10 KB

    const int tid = threadIdx.x;
    const int wid = tid >> 5;
    const int lane = tid & 31;
    const int gid = lane >> 2;       // 0..7
    const int tig = lane & 3;        // 0..3
    const int row0 = blockIdx.x << 7;   // 128 rows per block (row = t*N + n)

    // ---- B fragments from conv_w [64 x 32] (fp32 -> fp16 once) ----
    unsigned b[8][2][2];
#pragma unroll
    for (int nt = 0; nt < 8; nt++) {
        const int n0 = (nt << 3) + gid;
        const float* wr = conv_w + n0 * 32;
#pragma unroll
        for (int ks = 0; ks < 2; ks++) {
            const int k0 = (ks << 4) + (tig << 1);
            float2 lo = *(const float2*)(wr + k0);
            float2 hi = *(const float2*)(wr + k0 + 8);
            __half2 p0 = __floats2half2_rn(lo.x, lo.y);
            __half2 p1 = __floats2half2_rn(hi.x, hi.y);
            b[nt][ks][0] = *(unsigned*)&p0;
            b[nt][ks][1] = *(unsigned*)&p1;
        }
    }

    // ---- load x (f32) -> fp16 smem: 128 rows x 32 ch = 1024 float4 ----
    {
        const float4* x4 = (const float4*)x;
#pragma unroll
        for (int it = 0; it < 4; it++) {
            int idx = tid + (it << 8);
            int rl = idx >> 3, c4 = idx & 7;
            int row = row0 + rl;
            int t = row >> 11, n = row & (NN - 1);
            float4 v = x4[((n * TT + t) << 3) + c4];
            *(__half2*)(xs + rl * 40 + (c4 << 2))     = __floats2half2_rn(v.x, v.y);
            *(__half2*)(xs + rl * 40 + (c4 << 2) + 2) = __floats2half2_rn(v.z, v.w);
        }
    }
    __syncthreads();

    // ---- A fragments: warp owns 16 rows ----
    const int wbase = wid << 4;
    unsigned a[2][4];
#pragma unroll
    for (int ks = 0; ks < 2; ks++) {
        const int col = (ks << 4) + (tig << 1);
        a[ks][0] = *(const unsigned*)(xs + (wbase + gid) * 40 + col);
        a[ks][1] = *(const unsigned*)(xs + (wbase + gid + 8) * 40 + col);
        a[ks][2] = *(const unsigned*)(xs + (wbase + gid) * 40 + col + 8);
        a[ks][3] = *(const unsigned*)(xs + (wbase + gid + 8) * 40 + col + 8);
    }

#pragma unroll
    for (int nt = 0; nt < 8; nt++) {
        float c0 = 0.f, c1 = 0.f, c2 = 0.f, c3 = 0.f;
#pragma unroll
        for (int ks = 0; ks < 2; ks++) {
            asm volatile(
                "mma.sync.aligned.m16n8k16.row.col.f32.f16.f16.f32 "
                "{%0,%1,%2,%3}, {%4,%5,%6,%7}, {%8,%9}, {%0,%1,%2,%3};"
                : "+f"(c0), "+f"(c1), "+f"(c2), "+f"(c3)
                : "r"(a[ks][0]), "r"(a[ks][1]), "r"(a[ks][2]), "r"(a[ks][3]),
                  "r"(b[nt][ks][0]), "r"(b[nt][ks][1]));
        }
        const int col = (nt << 3) + (tig << 1);
        const int rA = row0 + wbase + gid;
        *(float2*)(g_z + ((size_t)rA << 6) + col)       = make_float2(c0, c1);
        *(float2*)(g_z + ((size_t)(rA + 8) << 6) + col) = make_float2(c2, c3);
        g_zh[(rA << 5) + (col >> 1)]       = __floats2half2_rn(c0, c1);
        g_zh[((rA + 8) << 5) + (col >> 1)] = __floats2half2_rn(c2, c3);
    }
}

// ---------------------------------------------------------------------------
// K23 (fused gather-max + tensor-core input GEMM): unchanged from R8.
// ---------------------------------------------------------------------------
__global__ __launch_bounds__(256) void k23_feat_gates(const int* __restrict__ A,
                                                      const float* __restrict__ conv_b,
                                                      const float* __restrict__ w_ih,
                                                      const float* __restrict__ b_ih,
                                                      const float* __restrict__ b_hh) {
    __shared__ __half fs[32 * 72];   // feat fp16, padded stride (4.5 KB)

    const int tid = threadIdx.x;
    const int lane = tid & 31;
    const int wrp = tid >> 5;
    const int gid = lane >> 2;       // 0..7
    const int tig = lane & 3;        // 0..3
    const int row0 = blockIdx.x << 5;
    const int nbase = wrp << 5;      // warp's 32 gate columns

    unsigned b[4][4][2];
    float2 biasv[4];
#pragma unroll
    for (int nt = 0; nt < 4; nt++) {
        const int n0 = nbase + (nt << 3) + gid;
        const float* wr = w_ih + n0 * 64;
#pragma unroll
        for (int ks = 0; ks < 4; ks++) {
            const int k0 = (ks << 4) + (tig << 1);
            float2 lo = *(const float2*)(wr + k0);
            float2 hi = *(const float2*)(wr + k0 + 8);
            __half2 p0 = __floats2half2_rn(lo.x, lo.y);
            __half2 p1 = __floats2half2_rn(hi.x, hi.y);
            b[nt][ks][0] = *(unsigned*)&p0;
            b[nt][ks][1] = *(unsigned*)&p1;
        }
        const int col = nbase + (nt << 3) + (tig << 1);
        biasv[nt].x = b_ih[col] + b_hh[col];
        biasv[nt].y = b_ih[col + 1] + b_hh[col + 1];
    }

    const float2 cb = ((const float2*)conv_b)[lane];

#pragma unroll
    for (int rr = 0; rr < 4; rr++) {
        const int row = row0 + (wrp << 2) + rr;
        const int t = row >> 11;
        const int nb = A[(row << 5) + lane];

        __half2 m = __float2half2_rn(-60000.f);
#pragma unroll
        for (int k = 0; k < KK; k++) {
            int r = __shfl_sync(0xffffffffu, nb, k);
            __half2 v = __ldg(&g_zh[(((t << 11) + r) << 5) + lane]);
            m = __hmax2(m, v);
        }
        float2 mf = __half22float2(m);
        float2 zc = ((const float2*)g_z)[(row << 5) + lane];
        *(__half2*)(fs + ((wrp << 2) + rr) * 72 + (lane << 1)) =
            __floats2half2_rn(mf.x - zc.x + cb.x, mf.y - zc.y + cb.y);
    }
    __syncthreads();

#pragma unroll
    for (int mt = 0; mt < 2; mt++) {
        const int rb = mt << 4;
        unsigned a[4][4];
#pragma unroll
        for (int ks = 0; ks < 4; ks++) {
            const int col = (ks << 4) + (tig << 1);
            a[ks][0] = *(const unsigned*)(fs + (rb + gid) * 72 + col);
            a[ks][1] = *(const unsigned*)(fs + (rb + gid + 8) * 72 + col);
            a[ks][2] = *(const unsigned*)(fs + (rb + gid) * 72 + col + 8);
            a[ks][3] = *(const unsigned*)(fs + (rb + gid + 8) * 72 + col + 8);
        }
#pragma unroll
        for (int nt = 0; nt < 4; nt++) {
            float c0 = 0.f, c1 = 0.f, c2 = 0.f, c3 = 0.f;
#pragma unroll
            for (int ks = 0; ks < 4; ks++) {
                asm volatile(
                    "mma.sync.aligned.m16n8k16.row.col.f32.f16.f16.f32 "
                    "{%0,%1,%2,%3}, {%4,%5,%6,%7}, {%8,%9}, {%0,%1,%2,%3};"
                    : "+f"(c0), "+f"(c1), "+f"(c2), "+f"(c3)
                    : "r"(a[ks][0]), "r"(a[ks][1]), "r"(a[ks][2]), "r"(a[ks][3]),
                      "r"(b[nt][ks][0]), "r"(b[nt][ks][1]));
            }
            const int col = nbase + (nt << 3) + (tig << 1);
            const int rowA = row0 + rb + gid;
            float2 lo = make_float2(c0 + biasv[nt].x, c1 + biasv[nt].y);
            float2 hi = make_float2(c2 + biasv[nt].x, c3 + biasv[nt].y);
            *(float2*)(g_gates + (size_t)rowA * G4 + col) = lo;
            *(float2*)(g_gates + (size_t)(rowA + 8) * G4 + col) = hi;
        }
    }
}

// ---------------------------------------------------------------------------
// K4: tensor-core LSTM, 256 blocks x 128 threads; block owns 8 agents
// (m16 MMA with upper 8 rows zero-padded; c2/c3 discarded). 2 blocks/SM so
// one block's barrier/memory stalls are covered by the other.
// ---------------------------------------------------------------------------
__global__ __launch_bounds__(128) void k4_lstm(const float* __restrict__ w_hh,
                                               float* __restrict__ out,
                                               int write_states) {
    __shared__ __half hs[16 * 68];   // h fp16 (rows 8-15 stay zero)
    __shared__ float  g_s[8 * 260];  // recurrent gate pre-acts, padded rows

    const int tid = threadIdx.x;
    const int wid = tid >> 5;       // 0..3
    const int lane = tid & 31;
    const int gid = lane >> 2;      // 0..7
    const int tig = lane & 3;       // 0..3
    const int ab = blockIdx.x << 3; // agent base (8 per block)
    const int nbase = wid << 6;     // warp's 64 output columns

    // ---- B fragments: 8 n-tiles x 4 k-steps ----
    unsigned b[8][4][2];
#pragma unroll
    for (int nt = 0; nt < 8; nt++) {
        const int n0 = nbase + (nt << 3) + gid;
        const float* wr = w_hh + n0 * 64;
#pragma unroll
        for (int ks = 0; ks < 4; ks++) {
            const int k0 = (ks << 4) + (tig << 1);
            float2 lo = *(const float2*)(wr + k0);
            float2 hi = *(const float2*)(wr + k0 + 8);
            __half2 p0 = __floats2half2_rn(lo.x, lo.y);
            __half2 p1 = __floats2half2_rn(hi.x, hi.y);
            b[nt][ks][0] = *(unsigned*)&p0;
            b[nt][ks][1] = *(unsigned*)&p1;
        }
    }

    for (int e = tid; e < 16 * 68; e += 128) hs[e] = __float2half(0.f);

    const int a_u = tid >> 4;   // 0..7
    const int q = tid & 15;     // 0..15
    float4 c4 = make_float4(0.f, 0.f, 0.f, 0.f);
    float4 h_last = make_float4(0.f, 0.f, 0.f, 0.f);
    __syncthreads();

    for (int t = 0; t < TT; t++) {
        // ---- prefetch gx for the update phase (hides L2 latency) ----
        const float* gx = g_gates + (((size_t)(t << 11) + ab + a_u) << 8) + (q << 2);
        float4 xi = *(const float4*)(gx);
        float4 xf = *(const float4*)(gx + 64);
        float4 xg = *(const float4*)(gx + 128);
        float4 xo = *(const float4*)(gx + 192);

        // ---- A fragments from hs (rows 8-15 zero) ----
        unsigned a[4][4];
#pragma unroll
        for (int ks = 0; ks < 4; ks++) {
            const int col = (ks << 4) + (tig << 1);
            a[ks][0] = *(const unsigned*)(hs + gid * 68 + col);
            a[ks][1] = *(const unsigned*)(hs + (gid + 8) * 68 + col);
            a[ks][2] = *(const unsigned*)(hs + gid * 68 + col + 8);
            a[ks][3] = *(const unsigned*)(hs + (gid + 8) * 68 + col + 8);
        }

#pragma unroll
        for (int nt = 0; nt < 8; nt++) {
            float c0 = 0.f, c1 = 0.f, c2 = 0.f, c3 = 0.f;
#pragma unroll
            for (int ks = 0; ks < 4; ks++) {
                asm volatile(
                    "mma.sync.aligned.m16n8k16.row.col.f32.f16.f16.f32 "
                    "{%0,%1,%2,%3}, {%4,%5,%6,%7}, {%8,%9}, {%0,%1,%2,%3};"
                    : "+f"(c0), "+f"(c1), "+f"(c2), "+f"(c3)
                    : "r"(a[ks][0]), "r"(a[ks][1]), "r"(a[ks][2]), "r"(a[ks][3]),
                      "r"(b[nt][ks][0]), "r"(b[nt][ks][1]));
            }
            const int col = nbase + (nt << 3) + (tig << 1);
            g_s[gid * 260 + col] = c0;        // rows 8-15 (c2/c3) discarded
            g_s[gid * 260 + col + 1] = c1;
        }
        __syncthreads();

        // ---- nonlinear update (gates i, f, g, o) ----
        const float* gr = g_s + a_u * 260 + (q << 2);
        float4 gi = *(const float4*)(gr);
        float4 gf = *(const float4*)(gr + 64);
        float4 gg = *(const float4*)(gr + 128);
        float4 go = *(const float4*)(gr + 192);
        gi.x += xi.x; gi.y += xi.y; gi.z += xi.z; gi.w += xi.w;
        gf.x += xf.x; gf.y += xf.y; gf.z += xf.z; gf.w += xf.w;
        gg.x += xg.x; gg.y += xg.y; gg.z += xg.z; gg.w += xg.w;
        go.x += xo.x; go.y += xo.y; go.z += xo.z; go.w += xo.w;

        c4.x = sigf(gf.x) * c4.x + sigf(gi.x) * tanhf_fast(gg.x);
        c4.y = sigf(gf.y) * c4.y + sigf(gi.y) * tanhf_fast(gg.y);
        c4.z = sigf(gf.z) * c4.z + sigf(gi.z) * tanhf_fast(gg.z);
        c4.w = sigf(gf.w) * c4.w + sigf(gi.w) * tanhf_fast(gg.w);

        float4 h4;
        h4.x = sigf(go.x) * tanhf_fast(c4.x);
        h4.y = sigf(go.y) * tanhf_fast(c4.y);
        h4.z = sigf(go.z) * tanhf_fast(c4.z);
        h4.w = sigf(go.w) * tanhf_fast(c4.w);
        h_last = h4;

        *(__half2*)(hs + a_u * 68 + (q << 2))     = __floats2half2_rn(h4.x, h4.y);
        *(__half2*)(hs + a_u * 68 + (q << 2) + 2) = __floats2half2_rn(h4.z, h4.w);
        *(float4*)(out + (((size_t)(ab + a_u) * TT + t) << 6) + (q << 2)) = h4;
        __syncthreads();
    }

    if (write_states) {
        float4* hn = (float4*)(out + (size_t)NN * TT * OO);
        float4* cn = (float4*)(out + (size_t)NN * TT * OO + (size_t)NN * OO);
        hn[((ab + a_u) << 4) + q] = h_last;
        cn[((ab + a_u) << 4) + q] = c4;
    }
}

// ---------------------------------------------------------------------------
extern "C" void kernel_launch(void* const* d_in, const int* in_sizes, int n_in,
                              void* d_out, int out_size) {
    const float* x      = (const float*)d_in[0];
    const int*   A      = (const int*)  d_in[1];
    const float* conv_w = (const float*)d_in[2];
    const float* conv_b = (const float*)d_in[3];
    const float* w_ih   = (const float*)d_in[4];
    const float* w_hh   = (const float*)d_in[5];
    const float* b_ih   = (const float*)d_in[6];
    const float* b_hh   = (const float*)d_in[7];
    float* out = (float*)d_out;

    const long main_sz = (long)NN * TT * OO;
    int write_states = (out_size >= main_sz + 2L * NN * OO) ? 1 : 0;

    k1_project<<<(TT * NN) / 128, 256>>>(x, conv_w);
    k23_feat_gates<<<(TT * NN) / 32, 256>>>(A, conv_b, w_ih, b_ih, b_hh);
    k4_lstm<<<NN / 8, 128>>>(w_hh, out, write_states);
}

// round 11
// speedup vs baseline: 3.3850x; 1.0661x over previous
#include <cuda_runtime.h>
#include <cuda_fp16.h>
#include <math.h>

#define NN 2048
#define TT 20
#define KK 32
#define CC 32
#define OO 64
#define G4 256   // 4*OO

// Scratch (static device globals; no runtime allocation)
__device__ __half2 g_zh[TT * NN * (OO/2)];  // z fp16 (only copy)
__device__ float   g_gates[TT * NN * G4];   // gates_x[t][n][0..255]

// NaN-safe fast sigmoid / tanh (rel err ~1e-7, 2 MUFU each)
__device__ __forceinline__ float sigf(float x) {
    return __fdividef(1.0f, 1.0f + __expf(-x));
}
__device__ __forceinline__ float tanhf_fast(float x) {
    return 1.0f - __fdividef(2.0f, __expf(2.0f * x) + 1.0f);
}

// ---------------------------------------------------------------------------
// K1 (tensor-core): z[rows x 64] = x[rows x 32] @ conv_w^T[32 x 64]
// 320 blocks x 256 threads; block owns 128 rows. x -> fp16 smem (stride 40);
// conv_w fp16 B-fragments; f32 accumulate; z stored fp16 ONLY.
// ---------------------------------------------------------------------------
__global__ __launch_bounds__(256) void k1_project(const float* __restrict__ x,
                                                  const float* __restrict__ conv_w) {
    __shared__ __half xs[128 * 40];   // 10 KB

    const int tid = threadIdx.x;
    const int wid = tid >> 5;
    const int lane = tid & 31;
    const int gid = lane >> 2;       // 0..7
    const int tig = lane & 3;        // 0..3
    const int row0 = blockIdx.x << 7;   // 128 rows per block (row = t*N + n)

    // ---- B fragments from conv_w [64 x 32] (fp32 -> fp16 once) ----
    unsigned b[8][2][2];
#pragma unroll
    for (int nt = 0; nt < 8; nt++) {
        const int n0 = (nt << 3) + gid;
        const float* wr = conv_w + n0 * 32;
#pragma unroll
        for (int ks = 0; ks < 2; ks++) {
            const int k0 = (ks << 4) + (tig << 1);
            float2 lo = *(const float2*)(wr + k0);
            float2 hi = *(const float2*)(wr + k0 + 8);
            __half2 p0 = __floats2half2_rn(lo.x, lo.y);
            __half2 p1 = __floats2half2_rn(hi.x, hi.y);
            b[nt][ks][0] = *(unsigned*)&p0;
            b[nt][ks][1] = *(unsigned*)&p1;
        }
    }

    // ---- load x (f32) -> fp16 smem: 128 rows x 32 ch = 1024 float4 ----
    {
        const float4* x4 = (const float4*)x;
#pragma unroll
        for (int it = 0; it < 4; it++) {
            int idx = tid + (it << 8);
            int rl = idx >> 3, c4 = idx & 7;
            int row = row0 + rl;
            int t = row >> 11, n = row & (NN - 1);
            float4 v = x4[((n * TT + t) << 3) + c4];
            *(__half2*)(xs + rl * 40 + (c4 << 2))     = __floats2half2_rn(v.x, v.y);
            *(__half2*)(xs + rl * 40 + (c4 << 2) + 2) = __floats2half2_rn(v.z, v.w);
        }
    }
    __syncthreads();

    // ---- A fragments: warp owns 16 rows ----
    const int wbase = wid << 4;
    unsigned a[2][4];
#pragma unroll
    for (int ks = 0; ks < 2; ks++) {
        const int col = (ks << 4) + (tig << 1);
        a[ks][0] = *(const unsigned*)(xs + (wbase + gid) * 40 + col);
        a[ks][1] = *(const unsigned*)(xs + (wbase + gid + 8) * 40 + col);
        a[ks][2] = *(const unsigned*)(xs + (wbase + gid) * 40 + col + 8);
        a[ks][3] = *(const unsigned*)(xs + (wbase + gid + 8) * 40 + col + 8);
    }

#pragma unroll
    for (int nt = 0; nt < 8; nt++) {
        float c0 = 0.f, c1 = 0.f, c2 = 0.f, c3 = 0.f;
#pragma unroll
        for (int ks = 0; ks < 2; ks++) {
            asm volatile(
                "mma.sync.aligned.m16n8k16.row.col.f32.f16.f16.f32 "
                "{%0,%1,%2,%3}, {%4,%5,%6,%7}, {%8,%9}, {%0,%1,%2,%3};"
                : "+f"(c0), "+f"(c1), "+f"(c2), "+f"(c3)
                : "r"(a[ks][0]), "r"(a[ks][1]), "r"(a[ks][2]), "r"(a[ks][3]),
                  "r"(b[nt][ks][0]), "r"(b[nt][ks][1]));
        }
        const int col = (nt << 3) + (tig << 1);
        const int rA = row0 + wbase + gid;
        g_zh[(rA << 5) + (col >> 1)]       = __floats2half2_rn(c0, c1);
        g_zh[((rA + 8) << 5) + (col >> 1)] = __floats2half2_rn(c2, c3);
    }
}

// ---------------------------------------------------------------------------
// K23 (fused gather-max + tensor-core input GEMM):
// Phase A: warp gather-maxes 4 rows in fp16; center term also from fp16 z;
//          feat -> fp16 smem (stride 72).
// Phase B: gates_x[32x256] = feat[32x64] @ w_ih^T via mma.sync, f32 accum,
//          bias epilogue, float2 stores.
// ---------------------------------------------------------------------------
__global__ __launch_bounds__(256) void k23_feat_gates(const int* __restrict__ A,
                                                      const float* __restrict__ conv_b,
                                                      const float* __restrict__ w_ih,
                                                      const float* __restrict__ b_ih,
                                                      const float* __restrict__ b_hh) {
    __shared__ __half fs[32 * 72];   // feat fp16, padded stride (4.5 KB)

    const int tid = threadIdx.x;
    const int lane = tid & 31;
    const int wrp = tid >> 5;
    const int gid = lane >> 2;       // 0..7
    const int tig = lane & 3;        // 0..3
    const int row0 = blockIdx.x << 5;
    const int nbase = wrp << 5;      // warp's 32 gate columns

    unsigned b[4][4][2];
    float2 biasv[4];
#pragma unroll
    for (int nt = 0; nt < 4; nt++) {
        const int n0 = nbase + (nt << 3) + gid;
        const float* wr = w_ih + n0 * 64;
#pragma unroll
        for (int ks = 0; ks < 4; ks++) {
            const int k0 = (ks << 4) + (tig << 1);
            float2 lo = *(const float2*)(wr + k0);
            float2 hi = *(const float2*)(wr + k0 + 8);
            __half2 p0 = __floats2half2_rn(lo.x, lo.y);
            __half2 p1 = __floats2half2_rn(hi.x, hi.y);
            b[nt][ks][0] = *(unsigned*)&p0;
            b[nt][ks][1] = *(unsigned*)&p1;
        }
        const int col = nbase + (nt << 3) + (tig << 1);
        biasv[nt].x = b_ih[col] + b_hh[col];
        biasv[nt].y = b_ih[col + 1] + b_hh[col + 1];
    }

    const float2 cb = ((const float2*)conv_b)[lane];

#pragma unroll
    for (int rr = 0; rr < 4; rr++) {
        const int row = row0 + (wrp << 2) + rr;
        const int t = row >> 11;
        const int nb = A[(row << 5) + lane];

        __half2 m = __float2half2_rn(-60000.f);
#pragma unroll
        for (int k = 0; k < KK; k++) {
            int r = __shfl_sync(0xffffffffu, nb, k);
            __half2 v = __ldg(&g_zh[(((t << 11) + r) << 5) + lane]);
            m = __hmax2(m, v);
        }
        float2 mf = __half22float2(m);
        float2 zc = __half22float2(g_zh[(row << 5) + lane]);
        *(__half2*)(fs + ((wrp << 2) + rr) * 72 + (lane << 1)) =
            __floats2half2_rn(mf.x - zc.x + cb.x, mf.y - zc.y + cb.y);
    }
    __syncthreads();

#pragma unroll
    for (int mt = 0; mt < 2; mt++) {
        const int rb = mt << 4;
        unsigned a[4][4];
#pragma unroll
        for (int ks = 0; ks < 4; ks++) {
            const int col = (ks << 4) + (tig << 1);
            a[ks][0] = *(const unsigned*)(fs + (rb + gid) * 72 + col);
            a[ks][1] = *(const unsigned*)(fs + (rb + gid + 8) * 72 + col);
            a[ks][2] = *(const unsigned*)(fs + (rb + gid) * 72 + col + 8);
            a[ks][3] = *(const unsigned*)(fs + (rb + gid + 8) * 72 + col + 8);
        }
#pragma unroll
        for (int nt = 0; nt < 4; nt++) {
            float c0 = 0.f, c1 = 0.f, c2 = 0.f, c3 = 0.f;
#pragma unroll
            for (int ks = 0; ks < 4; ks++) {
                asm volatile(
                    "mma.sync.aligned.m16n8k16.row.col.f32.f16.f16.f32 "
                    "{%0,%1,%2,%3}, {%4,%5,%6,%7}, {%8,%9}, {%0,%1,%2,%3};"
                    : "+f"(c0), "+f"(c1), "+f"(c2), "+f"(c3)
                    : "r"(a[ks][0]), "r"(a[ks][1]), "r"(a[ks][2]), "r"(a[ks][3]),
                      "r"(b[nt][ks][0]), "r"(b[nt][ks][1]));
            }
            const int col = nbase + (nt << 3) + (tig << 1);
            const int rowA = row0 + rb + gid;
            float2 lo = make_float2(c0 + biasv[nt].x, c1 + biasv[nt].y);
            float2 hi = make_float2(c2 + biasv[nt].x, c3 + biasv[nt].y);
            *(float2*)(g_gates + (size_t)rowA * G4 + col) = lo;
            *(float2*)(g_gates + (size_t)(rowA + 8) * G4 + col) = hi;
        }
    }
}

// ---------------------------------------------------------------------------
// K4: tensor-core LSTM (unchanged). 256 blocks x 128 threads; block owns
// 8 agents; m16 MMA (upper 8 rows zero), f32 update, c in registers.
// ---------------------------------------------------------------------------
__global__ __launch_bounds__(128) void k4_lstm(const float* __restrict__ w_hh,
                                               float* __restrict__ out,
                                               int write_states) {
    __shared__ __half hs[16 * 68];   // h fp16 (rows 8-15 stay zero)
    __shared__ float  g_s[8 * 260];  // recurrent gate pre-acts, padded rows

    const int tid = threadIdx.x;
    const int wid = tid >> 5;       // 0..3
    const int lane = tid & 31;
    const int gid = lane >> 2;      // 0..7
    const int tig = lane & 3;       // 0..3
    const int ab = blockIdx.x << 3; // agent base (8 per block)
    const int nbase = wid << 6;     // warp's 64 output columns

    unsigned b[8][4][2];
#pragma unroll
    for (int nt = 0; nt < 8; nt++) {
        const int n0 = nbase + (nt << 3) + gid;
        const float* wr = w_hh + n0 * 64;
#pragma unroll
        for (int ks = 0; ks < 4; ks++) {
            const int k0 = (ks << 4) + (tig << 1);
            float2 lo = *(const float2*)(wr + k0);
            float2 hi = *(const float2*)(wr + k0 + 8);
            __half2 p0 = __floats2half2_rn(lo.x, lo.y);
            __half2 p1 = __floats2half2_rn(hi.x, hi.y);
            b[nt][ks][0] = *(unsigned*)&p0;
            b[nt][ks][1] = *(unsigned*)&p1;
        }
    }

    for (int e = tid; e < 16 * 68; e += 128) hs[e] = __float2half(0.f);

    const int a_u = tid >> 4;   // 0..7
    const int q = tid & 15;     // 0..15
    float4 c4 = make_float4(0.f, 0.f, 0.f, 0.f);
    float4 h_last = make_float4(0.f, 0.f, 0.f, 0.f);
    __syncthreads();

    for (int t = 0; t < TT; t++) {
        const float* gx = g_gates + (((size_t)(t << 11) + ab + a_u) << 8) + (q << 2);
        float4 xi = *(const float4*)(gx);
        float4 xf = *(const float4*)(gx + 64);
        float4 xg = *(const float4*)(gx + 128);
        float4 xo = *(const float4*)(gx + 192);

        unsigned a[4][4];
#pragma unroll
        for (int ks = 0; ks < 4; ks++) {
            const int col = (ks << 4) + (tig << 1);
            a[ks][0] = *(const unsigned*)(hs + gid * 68 + col);
            a[ks][1] = *(const unsigned*)(hs + (gid + 8) * 68 + col);
            a[ks][2] = *(const unsigned*)(hs + gid * 68 + col + 8);
            a[ks][3] = *(const unsigned*)(hs + (gid + 8) * 68 + col + 8);
        }

#pragma unroll
        for (int nt = 0; nt < 8; nt++) {
            float c0 = 0.f, c1 = 0.f, c2 = 0.f, c3 = 0.f;
#pragma unroll
            for (int ks = 0; ks < 4; ks++) {
                asm volatile(
                    "mma.sync.aligned.m16n8k16.row.col.f32.f16.f16.f32 "
                    "{%0,%1,%2,%3}, {%4,%5,%6,%7}, {%8,%9}, {%0,%1,%2,%3};"
                    : "+f"(c0), "+f"(c1), "+f"(c2), "+f"(c3)
                    : "r"(a[ks][0]), "r"(a[ks][1]), "r"(a[ks][2]), "r"(a[ks][3]),
                      "r"(b[nt][ks][0]), "r"(b[nt][ks][1]));
            }
            const int col = nbase + (nt << 3) + (tig << 1);
            g_s[gid * 260 + col] = c0;        // rows 8-15 (c2/c3) discarded
            g_s[gid * 260 + col + 1] = c1;
        }
        __syncthreads();

        const float* gr = g_s + a_u * 260 + (q << 2);
        float4 gi = *(const float4*)(gr);
        float4 gf = *(const float4*)(gr + 64);
        float4 gg = *(const float4*)(gr + 128);
        float4 go = *(const float4*)(gr + 192);
        gi.x += xi.x; gi.y += xi.y; gi.z += xi.z; gi.w += xi.w;
        gf.x += xf.x; gf.y += xf.y; gf.z += xf.z; gf.w += xf.w;
        gg.x += xg.x; gg.y += xg.y; gg.z += xg.z; gg.w += xg.w;
        go.x += xo.x; go.y += xo.y; go.z += xo.z; go.w += xo.w;

        c4.x = sigf(gf.x) * c4.x + sigf(gi.x) * tanhf_fast(gg.x);
        c4.y = sigf(gf.y) * c4.y + sigf(gi.y) * tanhf_fast(gg.y);
        c4.z = sigf(gf.z) * c4.z + sigf(gi.z) * tanhf_fast(gg.z);
        c4.w = sigf(gf.w) * c4.w + sigf(gi.w) * tanhf_fast(gg.w);

        float4 h4;
        h4.x = sigf(go.x) * tanhf_fast(c4.x);
        h4.y = sigf(go.y) * tanhf_fast(c4.y);
        h4.z = sigf(go.z) * tanhf_fast(c4.z);
        h4.w = sigf(go.w) * tanhf_fast(c4.w);
        h_last = h4;

        *(__half2*)(hs + a_u * 68 + (q << 2))     = __floats2half2_rn(h4.x, h4.y);
        *(__half2*)(hs + a_u * 68 + (q << 2) + 2) = __floats2half2_rn(h4.z, h4.w);
        *(float4*)(out + (((size_t)(ab + a_u) * TT + t) << 6) + (q << 2)) = h4;
        __syncthreads();
    }

    if (write_states) {
        float4* hn = (float4*)(out + (size_t)NN * TT * OO);
        float4* cn = (float4*)(out + (size_t)NN * TT * OO + (size_t)NN * OO);
        hn[((ab + a_u) << 4) + q] = h_last;
        cn[((ab + a_u) << 4) + q] = c4;
    }
}

// ---------------------------------------------------------------------------
extern "C" void kernel_launch(void* const* d_in, const int* in_sizes, int n_in,
                              void* d_out, int out_size) {
    const float* x      = (const float*)d_in[0];
    const int*   A      = (const int*)  d_in[1];
    const float* conv_w = (const float*)d_in[2];
    const float* conv_b = (const float*)d_in[3];
    const float* w_ih   = (const float*)d_in[4];
    const float* w_hh   = (const float*)d_in[5];
    const float* b_ih   = (const float*)d_in[6];
    const float* b_hh   = (const float*)d_in[7];
    float* out = (float*)d_out;

    const long main_sz = (long)NN * TT * OO;
    int write_states = (out_size >= main_sz + 2L * NN * OO) ? 1 : 0;

    k1_project<<<(TT * NN) / 128, 256>>>(x, conv_w);
    k23_feat_gates<<<(TT * NN) / 32, 256>>>(A, conv_b, w_ih, b_ih, b_hh);
    k4_lstm<<<NN / 8, 128>>>(w_hh, out, write_states);
}

// round 12
// speedup vs baseline: 3.4329x; 1.0142x over previous
#include <cuda_runtime.h>
#include <cuda_fp16.h>
#include <math.h>

#define NN 2048
#define TT 20
#define KK 32
#define CC 32
#define OO 64
#define G4 256   // 4*OO

// Scratch (static device globals; no runtime allocation)
__device__ __half2 g_zh[TT * NN * (OO/2)];   // z fp16 (only copy)
__device__ __half  g_gatesh[TT * NN * G4];   // gates_x fp16

// NaN-safe fast sigmoid / tanh (rel err ~1e-7, 2 MUFU each)
__device__ __forceinline__ float sigf(float x) {
    return __fdividef(1.0f, 1.0f + __expf(-x));
}
__device__ __forceinline__ float tanhf_fast(float x) {
    return 1.0f - __fdividef(2.0f, __expf(2.0f * x) + 1.0f);
}
__device__ __forceinline__ float4 ld_half4(const __half* p) {
    __half2 a = *(const __half2*)p;
    __half2 b = *(const __half2*)(p + 2);
    float2 fa = __half22float2(a), fb = __half22float2(b);
    return make_float4(fa.x, fa.y, fb.x, fb.y);
}

// ---------------------------------------------------------------------------
// K1 (tensor-core): z[rows x 64] = x[rows x 32] @ conv_w^T[32 x 64]
// 320 blocks x 256 threads; block owns 128 rows. x -> fp16 smem (stride 40);
// conv_w fp16 B-fragments; f32 accumulate. Results staged in smem (stride 72,
// conflict-free epilogue stores) then written back as coalesced 16B stores.
// ---------------------------------------------------------------------------
__global__ __launch_bounds__(256) void k1_project(const float* __restrict__ x,
                                                  const float* __restrict__ conv_w) {
    __shared__ __half xs[128 * 40];   // 10 KB
    __shared__ __half zs[128 * 72];   // 18 KB staging for z

    const int tid = threadIdx.x;
    const int wid = tid >> 5;
    const int lane = tid & 31;
    const int gid = lane >> 2;       // 0..7
    const int tig = lane & 3;        // 0..3
    const int row0 = blockIdx.x << 7;   // 128 rows per block (row = t*N + n)

    // ---- B fragments from conv_w [64 x 32] (fp32 -> fp16 once) ----
    unsigned b[8][2][2];
#pragma unroll
    for (int nt = 0; nt < 8; nt++) {
        const int n0 = (nt << 3) + gid;
        const float* wr = conv_w + n0 * 32;
#pragma unroll
        for (int ks = 0; ks < 2; ks++) {
            const int k0 = (ks << 4) + (tig << 1);
            float2 lo = *(const float2*)(wr + k0);
            float2 hi = *(const float2*)(wr + k0 + 8);
            __half2 p0 = __floats2half2_rn(lo.x, lo.y);
            __half2 p1 = __floats2half2_rn(hi.x, hi.y);
            b[nt][ks][0] = *(unsigned*)&p0;
            b[nt][ks][1] = *(unsigned*)&p1;
        }
    }

    // ---- load x (f32) -> fp16 smem: 128 rows x 32 ch = 1024 float4 ----
    {
        const float4* x4 = (const float4*)x;
#pragma unroll
        for (int it = 0; it < 4; it++) {
            int idx = tid + (it << 8);
            int rl = idx >> 3, c4 = idx & 7;
            int row = row0 + rl;
            int t = row >> 11, n = row & (NN - 1);
            float4 v = x4[((n * TT + t) << 3) + c4];
            *(__half2*)(xs + rl * 40 + (c4 << 2))     = __floats2half2_rn(v.x, v.y);
            *(__half2*)(xs + rl * 40 + (c4 << 2) + 2) = __floats2half2_rn(v.z, v.w);
        }
    }
    __syncthreads();

    // ---- A fragments: warp owns 16 rows ----
    const int wbase = wid << 4;
    unsigned a[2][4];
#pragma unroll
    for (int ks = 0; ks < 2; ks++) {
        const int col = (ks << 4) + (tig << 1);
        a[ks][0] = *(const unsigned*)(xs + (wbase + gid) * 40 + col);
        a[ks][1] = *(const unsigned*)(xs + (wbase + gid + 8) * 40 + col);
        a[ks][2] = *(const unsigned*)(xs + (wbase + gid) * 40 + col + 8);
        a[ks][3] = *(const unsigned*)(xs + (wbase + gid + 8) * 40 + col + 8);
    }

#pragma unroll
    for (int nt = 0; nt < 8; nt++) {
        float c0 = 0.f, c1 = 0.f, c2 = 0.f, c3 = 0.f;
#pragma unroll
        for (int ks = 0; ks < 2; ks++) {
            asm volatile(
                "mma.sync.aligned.m16n8k16.row.col.f32.f16.f16.f32 "
                "{%0,%1,%2,%3}, {%4,%5,%6,%7}, {%8,%9}, {%0,%1,%2,%3};"
                : "+f"(c0), "+f"(c1), "+f"(c2), "+f"(c3)
                : "r"(a[ks][0]), "r"(a[ks][1]), "r"(a[ks][2]), "r"(a[ks][3]),
                  "r"(b[nt][ks][0]), "r"(b[nt][ks][1]));
        }
        const int col = (nt << 3) + (tig << 1);
        *(__half2*)(zs + (wbase + gid) * 72 + col)     = __floats2half2_rn(c0, c1);
        *(__half2*)(zs + (wbase + gid + 8) * 72 + col) = __floats2half2_rn(c2, c3);
    }
    __syncthreads();

    // ---- coalesced writeback: 128 rows x 128B = 1024 x 16B ----
    {
        uint4* zg = ((uint4*)g_zh) + ((size_t)row0 << 3);
#pragma unroll
        for (int it = 0; it < 4; it++) {
            int idx = tid + (it << 8);
            int rl = idx >> 3, c = idx & 7;
            zg[idx] = ((const uint4*)(zs + rl * 72))[c];
        }
    }
}

// ---------------------------------------------------------------------------
// K23 (fused gather-max + tensor-core input GEMM): gates stored fp16.
// ---------------------------------------------------------------------------
__global__ __launch_bounds__(256) void k23_feat_gates(const int* __restrict__ A,
                                                      const float* __restrict__ conv_b,
                                                      const float* __restrict__ w_ih,
                                                      const float* __restrict__ b_ih,
                                                      const float* __restrict__ b_hh) {
    __shared__ __half fs[32 * 72];   // feat fp16, padded stride (4.5 KB)

    const int tid = threadIdx.x;
    const int lane = tid & 31;
    const int wrp = tid >> 5;
    const int gid = lane >> 2;       // 0..7
    const int tig = lane & 3;        // 0..3
    const int row0 = blockIdx.x << 5;
    const int nbase = wrp << 5;      // warp's 32 gate columns

    unsigned b[4][4][2];
    float2 biasv[4];
#pragma unroll
    for (int nt = 0; nt < 4; nt++) {
        const int n0 = nbase + (nt << 3) + gid;
        const float* wr = w_ih + n0 * 64;
#pragma unroll
        for (int ks = 0; ks < 4; ks++) {
            const int k0 = (ks << 4) + (tig << 1);
            float2 lo = *(const float2*)(wr + k0);
            float2 hi = *(const float2*)(wr + k0 + 8);
            __half2 p0 = __floats2half2_rn(lo.x, lo.y);
            __half2 p1 = __floats2half2_rn(hi.x, hi.y);
            b[nt][ks][0] = *(unsigned*)&p0;
            b[nt][ks][1] = *(unsigned*)&p1;
        }
        const int col = nbase + (nt << 3) + (tig << 1);
        biasv[nt].x = b_ih[col] + b_hh[col];
        biasv[nt].y = b_ih[col + 1] + b_hh[col + 1];
    }

    const float2 cb = ((const float2*)conv_b)[lane];

#pragma unroll
    for (int rr = 0; rr < 4; rr++) {
        const int row = row0 + (wrp << 2) + rr;
        const int t = row >> 11;
        const int nb = A[(row << 5) + lane];

        __half2 m = __float2half2_rn(-60000.f);
#pragma unroll
        for (int k = 0; k < KK; k++) {
            int r = __shfl_sync(0xffffffffu, nb, k);
            __half2 v = __ldg(&g_zh[(((t << 11) + r) << 5) + lane]);
            m = __hmax2(m, v);
        }
        float2 mf = __half22float2(m);
        float2 zc = __half22float2(g_zh[(row << 5) + lane]);
        *(__half2*)(fs + ((wrp << 2) + rr) * 72 + (lane << 1)) =
            __floats2half2_rn(mf.x - zc.x + cb.x, mf.y - zc.y + cb.y);
    }
    __syncthreads();

#pragma unroll
    for (int mt = 0; mt < 2; mt++) {
        const int rb = mt << 4;
        unsigned a[4][4];
#pragma unroll
        for (int ks = 0; ks < 4; ks++) {
            const int col = (ks << 4) + (tig << 1);
            a[ks][0] = *(const unsigned*)(fs + (rb + gid) * 72 + col);
            a[ks][1] = *(const unsigned*)(fs + (rb + gid + 8) * 72 + col);
            a[ks][2] = *(const unsigned*)(fs + (rb + gid) * 72 + col + 8);
            a[ks][3] = *(const unsigned*)(fs + (rb + gid + 8) * 72 + col + 8);
        }
#pragma unroll
        for (int nt = 0; nt < 4; nt++) {
            float c0 = 0.f, c1 = 0.f, c2 = 0.f, c3 = 0.f;
#pragma unroll
            for (int ks = 0; ks < 4; ks++) {
                asm volatile(
                    "mma.sync.aligned.m16n8k16.row.col.f32.f16.f16.f32 "
                    "{%0,%1,%2,%3}, {%4,%5,%6,%7}, {%8,%9}, {%0,%1,%2,%3};"
                    : "+f"(c0), "+f"(c1), "+f"(c2), "+f"(c3)
                    : "r"(a[ks][0]), "r"(a[ks][1]), "r"(a[ks][2]), "r"(a[ks][3]),
                      "r"(b[nt][ks][0]), "r"(b[nt][ks][1]));
            }
            const int col = nbase + (nt << 3) + (tig << 1);
            const int rowA = row0 + rb + gid;
            *(__half2*)(g_gatesh + (size_t)rowA * G4 + col) =
                __floats2half2_rn(c0 + biasv[nt].x, c1 + biasv[nt].y);
            *(__half2*)(g_gatesh + (size_t)(rowA + 8) * G4 + col) =
                __floats2half2_rn(c2 + biasv[nt].x, c3 + biasv[nt].y);
        }
    }
}

// ---------------------------------------------------------------------------
// K4: tensor-core LSTM. 256 blocks x 128 threads; block owns 8 agents;
// m16 MMA (upper 8 rows zero), f32 update, c in registers; gx read fp16.
// ---------------------------------------------------------------------------
__global__ __launch_bounds__(128) void k4_lstm(const float* __restrict__ w_hh,
                                               float* __restrict__ out,
                                               int write_states) {
    __shared__ __half hs[16 * 68];   // h fp16 (rows 8-15 stay zero)
    __shared__ float  g_s[8 * 260];  // recurrent gate pre-acts, padded rows

    const int tid = threadIdx.x;
    const int wid = tid >> 5;       // 0..3
    const int lane = tid & 31;
    const int gid = lane >> 2;      // 0..7
    const int tig = lane & 3;       // 0..3
    const int ab = blockIdx.x << 3; // agent base (8 per block)
    const int nbase = wid << 6;     // warp's 64 output columns

    unsigned b[8][4][2];
#pragma unroll
    for (int nt = 0; nt < 8; nt++) {
        const int n0 = nbase + (nt << 3) + gid;
        const float* wr = w_hh + n0 * 64;
#pragma unroll
        for (int ks = 0; ks < 4; ks++) {
            const int k0 = (ks << 4) + (tig << 1);
            float2 lo = *(const float2*)(wr + k0);
            float2 hi = *(const float2*)(wr + k0 + 8);
            __half2 p0 = __floats2half2_rn(lo.x, lo.y);
            __half2 p1 = __floats2half2_rn(hi.x, hi.y);
            b[nt][ks][0] = *(unsigned*)&p0;
            b[nt][ks][1] = *(unsigned*)&p1;
        }
    }

    for (int e = tid; e < 16 * 68; e += 128) hs[e] = __float2half(0.f);

    const int a_u = tid >> 4;   // 0..7
    const int q = tid & 15;     // 0..15
    float4 c4 = make_float4(0.f, 0.f, 0.f, 0.f);
    float4 h_last = make_float4(0.f, 0.f, 0.f, 0.f);
    __syncthreads();

    for (int t = 0; t < TT; t++) {
        // ---- prefetch gx (fp16) for the update phase ----
        const __half* gx = g_gatesh + (((size_t)(t << 11) + ab + a_u) << 8) + (q << 2);
        float4 xi = ld_half4(gx);
        float4 xf = ld_half4(gx + 64);
        float4 xg = ld_half4(gx + 128);
        float4 xo = ld_half4(gx + 192);

        unsigned a[4][4];
#pragma unroll
        for (int ks = 0; ks < 4; ks++) {
            const int col = (ks << 4) + (tig << 1);
            a[ks][0] = *(const unsigned*)(hs + gid * 68 + col);
            a[ks][1] = *(const unsigned*)(hs + (gid + 8) * 68 + col);
            a[ks][2] = *(const unsigned*)(hs + gid * 68 + col + 8);
            a[ks][3] = *(const unsigned*)(hs + (gid + 8) * 68 + col + 8);
        }

#pragma unroll
        for (int nt = 0; nt < 8; nt++) {
            float c0 = 0.f, c1 = 0.f, c2 = 0.f, c3 = 0.f;
#pragma unroll
            for (int ks = 0; ks < 4; ks++) {
                asm volatile(
                    "mma.sync.aligned.m16n8k16.row.col.f32.f16.f16.f32 "
                    "{%0,%1,%2,%3}, {%4,%5,%6,%7}, {%8,%9}, {%0,%1,%2,%3};"
                    : "+f"(c0), "+f"(c1), "+f"(c2), "+f"(c3)
                    : "r"(a[ks][0]), "r"(a[ks][1]), "r"(a[ks][2]), "r"(a[ks][3]),
                      "r"(b[nt][ks][0]), "r"(b[nt][ks][1]));
            }
            const int col = nbase + (nt << 3) + (tig << 1);
            g_s[gid * 260 + col] = c0;        // rows 8-15 (c2/c3) discarded
            g_s[gid * 260 + col + 1] = c1;
        }
        __syncthreads();

        const float* gr = g_s + a_u * 260 + (q << 2);
        float4 gi = *(const float4*)(gr);
        float4 gf = *(const float4*)(gr + 64);
        float4 gg = *(const float4*)(gr + 128);
        float4 go = *(const float4*)(gr + 192);
        gi.x += xi.x; gi.y += xi.y; gi.z += xi.z; gi.w += xi.w;
        gf.x += xf.x; gf.y += xf.y; gf.z += xf.z; gf.w += xf.w;
        gg.x += xg.x; gg.y += xg.y; gg.z += xg.z; gg.w += xg.w;
        go.x += xo.x; go.y += xo.y; go.z += xo.z; go.w += xo.w;

        c4.x = sigf(gf.x) * c4.x + sigf(gi.x) * tanhf_fast(gg.x);
        c4.y = sigf(gf.y) * c4.y + sigf(gi.y) * tanhf_fast(gg.y);
        c4.z = sigf(gf.z) * c4.z + sigf(gi.z) * tanhf_fast(gg.z);
        c4.w = sigf(gf.w) * c4.w + sigf(gi.w) * tanhf_fast(gg.w);

        float4 h4;
        h4.x = sigf(go.x) * tanhf_fast(c4.x);
        h4.y = sigf(go.y) * tanhf_fast(c4.y);
        h4.z = sigf(go.z) * tanhf_fast(c4.z);
        h4.w = sigf(go.w) * tanhf_fast(c4.w);
        h_last = h4;

        *(__half2*)(hs + a_u * 68 + (q << 2))     = __floats2half2_rn(h4.x, h4.y);
        *(__half2*)(hs + a_u * 68 + (q << 2) + 2) = __floats2half2_rn(h4.z, h4.w);
        *(float4*)(out + (((size_t)(ab + a_u) * TT + t) << 6) + (q << 2)) = h4;
        __syncthreads();
    }

    if (write_states) {
        float4* hn = (float4*)(out + (size_t)NN * TT * OO);
        float4* cn = (float4*)(out + (size_t)NN * TT * OO + (size_t)NN * OO);
        hn[((ab + a_u) << 4) + q] = h_last;
        cn[((ab + a_u) << 4) + q] = c4;
    }
}

// ---------------------------------------------------------------------------
extern "C" void kernel_launch(void* const* d_in, const int* in_sizes, int n_in,
                              void* d_out, int out_size) {
    const float* x      = (const float*)d_in[0];
    const int*   A      = (const int*)  d_in[1];
    const float* conv_w = (const float*)d_in[2];
    const float* conv_b = (const float*)d_in[3];
    const float* w_ih   = (const float*)d_in[4];
    const float* w_hh   = (const float*)d_in[5];
    const float* b_ih   = (const float*)d_in[6];
    const float* b_hh   = (const float*)d_in[7];
    float* out = (float*)d_out;

    const long main_sz = (long)NN * TT * OO;
    int write_states = (out_size >= main_sz + 2L * NN * OO) ? 1 : 0;

    k1_project<<<(TT * NN) / 128, 256>>>(x, conv_w);
    k23_feat_gates<<<(TT * NN) / 32, 256>>>(A, conv_b, w_ih, b_ih, b_hh);
    k4_lstm<<<NN / 8, 128>>>(w_hh, out, write_states);
}

// round 13
// speedup vs baseline: 3.9011x; 1.1364x over previous
#include <cuda_runtime.h>
#include <cuda_fp16.h>
#include <math.h>

#define NN 2048
#define TT 20
#define KK 32
#define CC 32
#define OO 64
#define G4 256   // 4*OO

// Scratch (static device globals; no runtime allocation)
__device__ __half2 g_zh[TT * NN * (OO/2)];   // z fp16 (only intermediate)

// NaN-safe fast sigmoid / tanh (rel err ~1e-7, 2 MUFU each)
__device__ __forceinline__ float sigf(float x) {
    return __fdividef(1.0f, 1.0f + __expf(-x));
}
__device__ __forceinline__ float tanhf_fast(float x) {
    return 1.0f - __fdividef(2.0f, __expf(2.0f * x) + 1.0f);
}

// ---------------------------------------------------------------------------
// K1 (tensor-core): z[rows x 64] = x[rows x 32] @ conv_w^T[32 x 64]
// 320 blocks x 256 threads; block owns 128 rows; z staged in smem then
// written back as coalesced 16B fp16 stores. (unchanged from R12)
// ---------------------------------------------------------------------------
__global__ __launch_bounds__(256) void k1_project(const float* __restrict__ x,
                                                  const float* __restrict__ conv_w) {
    __shared__ __half xs[128 * 40];   // 10 KB
    __shared__ __half zs[128 * 72];   // 18 KB staging for z

    const int tid = threadIdx.x;
    const int wid = tid >> 5;
    const int lane = tid & 31;
    const int gid = lane >> 2;       // 0..7
    const int tig = lane & 3;        // 0..3
    const int row0 = blockIdx.x << 7;   // 128 rows per block (row = t*N + n)

    unsigned b[8][2][2];
#pragma unroll
    for (int nt = 0; nt < 8; nt++) {
        const int n0 = (nt << 3) + gid;
        const float* wr = conv_w + n0 * 32;
#pragma unroll
        for (int ks = 0; ks < 2; ks++) {
            const int k0 = (ks << 4) + (tig << 1);
            float2 lo = *(const float2*)(wr + k0);
            float2 hi = *(const float2*)(wr + k0 + 8);
            __half2 p0 = __floats2half2_rn(lo.x, lo.y);
            __half2 p1 = __floats2half2_rn(hi.x, hi.y);
            b[nt][ks][0] = *(unsigned*)&p0;
            b[nt][ks][1] = *(unsigned*)&p1;
        }
    }

    {
        const float4* x4 = (const float4*)x;
#pragma unroll
        for (int it = 0; it < 4; it++) {
            int idx = tid + (it << 8);
            int rl = idx >> 3, c4 = idx & 7;
            int row = row0 + rl;
            int t = row >> 11, n = row & (NN - 1);
            float4 v = x4[((n * TT + t) << 3) + c4];
            *(__half2*)(xs + rl * 40 + (c4 << 2))     = __floats2half2_rn(v.x, v.y);
            *(__half2*)(xs + rl * 40 + (c4 << 2) + 2) = __floats2half2_rn(v.z, v.w);
        }
    }
    __syncthreads();

    const int wbase = wid << 4;
    unsigned a[2][4];
#pragma unroll
    for (int ks = 0; ks < 2; ks++) {
        const int col = (ks << 4) + (tig << 1);
        a[ks][0] = *(const unsigned*)(xs + (wbase + gid) * 40 + col);
        a[ks][1] = *(const unsigned*)(xs + (wbase + gid + 8) * 40 + col);
        a[ks][2] = *(const unsigned*)(xs + (wbase + gid) * 40 + col + 8);
        a[ks][3] = *(const unsigned*)(xs + (wbase + gid + 8) * 40 + col + 8);
    }

#pragma unroll
    for (int nt = 0; nt < 8; nt++) {
        float c0 = 0.f, c1 = 0.f, c2 = 0.f, c3 = 0.f;
#pragma unroll
        for (int ks = 0; ks < 2; ks++) {
            asm volatile(
                "mma.sync.aligned.m16n8k16.row.col.f32.f16.f16.f32 "
                "{%0,%1,%2,%3}, {%4,%5,%6,%7}, {%8,%9}, {%0,%1,%2,%3};"
                : "+f"(c0), "+f"(c1), "+f"(c2), "+f"(c3)
                : "r"(a[ks][0]), "r"(a[ks][1]), "r"(a[ks][2]), "r"(a[ks][3]),
                  "r"(b[nt][ks][0]), "r"(b[nt][ks][1]));
        }
        const int col = (nt << 3) + (tig << 1);
        *(__half2*)(zs + (wbase + gid) * 72 + col)     = __floats2half2_rn(c0, c1);
        *(__half2*)(zs + (wbase + gid + 8) * 72 + col) = __floats2half2_rn(c2, c3);
    }
    __syncthreads();

    {
        uint4* zg = ((uint4*)g_zh) + ((size_t)row0 << 3);
#pragma unroll
        for (int it = 0; it < 4; it++) {
            int idx = tid + (it << 8);
            int rl = idx >> 3, c = idx & 7;
            zg[idx] = ((const uint4*)(zs + rl * 72))[c];
        }
    }
}

// ---------------------------------------------------------------------------
// K234 (fused gather + input GEMM + LSTM): 256 blocks x 128 threads; block
// owns 8 agents for all 20 steps; 2 blocks/SM.
// Per step: (1) warps gather-max feat(t) for 2 rows each into smA cols 0-63;
// (2) one concatenated MMA chain: gates = [feat | h] @ [w_ih | w_hh]^T
//     (K=128, 8 k-steps; B fragments in registers; upper 8 MMA rows zero);
// (3) f32 LSTM update, h written back to smA cols 64-127 fp16, out f32.
// g_gates global intermediate is eliminated entirely.
// ---------------------------------------------------------------------------
__global__ __launch_bounds__(128, 2) void k234_lstm(const int* __restrict__ A,
                                                    const float* __restrict__ conv_b,
                                                    const float* __restrict__ w_ih,
                                                    const float* __restrict__ w_hh,
                                                    const float* __restrict__ b_ih,
                                                    const float* __restrict__ b_hh,
                                                    float* __restrict__ out,
                                                    int write_states) {
    __shared__ __half smA[16 * 136];   // rows 0-7: [feat | h]; rows 8-15 zero
    __shared__ float  g_s[8 * 260];    // gate pre-activations staging

    const int tid = threadIdx.x;
    const int wid = tid >> 5;        // 0..3
    const int lane = tid & 31;
    const int gid = lane >> 2;       // 0..7
    const int tig = lane & 3;        // 0..3
    const int ab = blockIdx.x << 3;  // agent base (8 per block)
    const int nbase = wid << 6;      // warp's 64 gate columns

    // ---- B fragments: concat [w_ih | w_hh] rows, K=128 (8 k-steps) ----
    unsigned b[8][8][2];
    float2 biasv[8];
#pragma unroll
    for (int nt = 0; nt < 8; nt++) {
        const int n0 = nbase + (nt << 3) + gid;
#pragma unroll
        for (int ks = 0; ks < 8; ks++) {
            const float* wr = (ks < 4 ? w_ih : w_hh) + n0 * 64;
            const int k0 = ((ks & 3) << 4) + (tig << 1);
            float2 lo = *(const float2*)(wr + k0);
            float2 hi = *(const float2*)(wr + k0 + 8);
            __half2 p0 = __floats2half2_rn(lo.x, lo.y);
            __half2 p1 = __floats2half2_rn(hi.x, hi.y);
            b[nt][ks][0] = *(unsigned*)&p0;
            b[nt][ks][1] = *(unsigned*)&p1;
        }
        const int col = nbase + (nt << 3) + (tig << 1);
        biasv[nt].x = b_ih[col] + b_hh[col];
        biasv[nt].y = b_ih[col + 1] + b_hh[col + 1];
    }

    for (int e = tid; e < 16 * 136; e += 128) smA[e] = __float2half(0.f);

    const float2 cb = ((const float2*)conv_b)[lane];
    const int a_u = tid >> 4;   // 0..7 (update-phase agent)
    const int q = tid & 15;     // 0..15 (4-channel chunk)
    float4 c4 = make_float4(0.f, 0.f, 0.f, 0.f);
    float4 h_last = make_float4(0.f, 0.f, 0.f, 0.f);
    __syncthreads();

    for (int t = 0; t < TT; t++) {
        // ---- gather-max feat(t): warp handles agents 2*wid, 2*wid+1 ----
#pragma unroll
        for (int rr = 0; rr < 2; rr++) {
            const int a = (wid << 1) + rr;
            const int row = (t << 11) + ab + a;
            const int nb = A[(row << 5) + lane];
            __half2 m = __float2half2_rn(-60000.f);
#pragma unroll
            for (int k = 0; k < KK; k++) {
                int r = __shfl_sync(0xffffffffu, nb, k);
                __half2 v = __ldg(&g_zh[(((t << 11) + r) << 5) + lane]);
                m = __hmax2(m, v);
            }
            float2 mf = __half22float2(m);
            float2 zc = __half22float2(g_zh[(row << 5) + lane]);
            *(__half2*)(smA + a * 136 + (lane << 1)) =
                __floats2half2_rn(mf.x - zc.x + cb.x, mf.y - zc.y + cb.y);
        }
        __syncthreads();   // feat(t) + h(t-1) ready

        // ---- concatenated MMA: gates = [feat | h] @ [w_ih | w_hh]^T ----
        unsigned afr[8][4];
#pragma unroll
        for (int ks = 0; ks < 8; ks++) {
            const int col = (ks << 4) + (tig << 1);
            afr[ks][0] = *(const unsigned*)(smA + gid * 136 + col);
            afr[ks][1] = *(const unsigned*)(smA + (gid + 8) * 136 + col);
            afr[ks][2] = *(const unsigned*)(smA + gid * 136 + col + 8);
            afr[ks][3] = *(const unsigned*)(smA + (gid + 8) * 136 + col + 8);
        }
#pragma unroll
        for (int nt = 0; nt < 8; nt++) {
            float c0 = 0.f, c1 = 0.f, c2 = 0.f, c3 = 0.f;
#pragma unroll
            for (int ks = 0; ks < 8; ks++) {
                asm volatile(
                    "mma.sync.aligned.m16n8k16.row.col.f32.f16.f16.f32 "
                    "{%0,%1,%2,%3}, {%4,%5,%6,%7}, {%8,%9}, {%0,%1,%2,%3};"
                    : "+f"(c0), "+f"(c1), "+f"(c2), "+f"(c3)
                    : "r"(afr[ks][0]), "r"(afr[ks][1]), "r"(afr[ks][2]), "r"(afr[ks][3]),
                      "r"(b[nt][ks][0]), "r"(b[nt][ks][1]));
            }
            const int col = nbase + (nt << 3) + (tig << 1);
            g_s[gid * 260 + col]     = c0 + biasv[nt].x;   // rows 8-15 discarded
            g_s[gid * 260 + col + 1] = c1 + biasv[nt].y;
        }
        __syncthreads();   // g_s ready

        // ---- nonlinear update (gates i, f, g, o) ----
        const float* gr = g_s + a_u * 260 + (q << 2);
        float4 gi = *(const float4*)(gr);
        float4 gf = *(const float4*)(gr + 64);
        float4 gg = *(const float4*)(gr + 128);
        float4 go = *(const float4*)(gr + 192);

        c4.x = sigf(gf.x) * c4.x + sigf(gi.x) * tanhf_fast(gg.x);
        c4.y = sigf(gf.y) * c4.y + sigf(gi.y) * tanhf_fast(gg.y);
        c4.z = sigf(gf.z) * c4.z + sigf(gi.z) * tanhf_fast(gg.z);
        c4.w = sigf(gf.w) * c4.w + sigf(gi.w) * tanhf_fast(gg.w);

        float4 h4;
        h4.x = sigf(go.x) * tanhf_fast(c4.x);
        h4.y = sigf(go.y) * tanhf_fast(c4.y);
        h4.z = sigf(go.z) * tanhf_fast(c4.z);
        h4.w = sigf(go.w) * tanhf_fast(c4.w);
        h_last = h4;

        // h -> smA cols 64-127 (read by next step's MMA, after barrier-1)
        *(__half2*)(smA + a_u * 136 + 64 + (q << 2))     = __floats2half2_rn(h4.x, h4.y);
        *(__half2*)(smA + a_u * 136 + 64 + (q << 2) + 2) = __floats2half2_rn(h4.z, h4.w);
        *(float4*)(out + (((size_t)(ab + a_u) * TT + t) << 6) + (q << 2)) = h4;
        // no barrier here: next gather writes cols 0-63 only (disjoint from
        // g_s and from h cols); barrier-1 of t+1 orders h/feat vs MMA reads.
    }

    if (write_states) {
        float4* hn = (float4*)(out + (size_t)NN * TT * OO);
        float4* cn = (float4*)(out + (size_t)NN * TT * OO + (size_t)NN * OO);
        hn[((ab + a_u) << 4) + q] = h_last;
        cn[((ab + a_u) << 4) + q] = c4;
    }
}

// ---------------------------------------------------------------------------
extern "C" void kernel_launch(void* const* d_in, const int* in_sizes, int n_in,
                              void* d_out, int out_size) {
    const float* x      = (const float*)d_in[0];
    const int*   A      = (const int*)  d_in[1];
    const float* conv_w = (const float*)d_in[2];
    const float* conv_b = (const float*)d_in[3];
    const float* w_ih   = (const float*)d_in[4];
    const float* w_hh   = (const float*)d_in[5];
    const float* b_ih   = (const float*)d_in[6];
    const float* b_hh   = (const float*)d_in[7];
    float* out = (float*)d_out;

    const long main_sz = (long)NN * TT * OO;
    int write_states = (out_size >= main_sz + 2L * NN * OO) ? 1 : 0;

    k1_project<<<(TT * NN) / 128, 256>>>(x, conv_w);
    k234_lstm<<<NN / 8, 128>>>(A, conv_b, w_ih, w_hh, b_ih, b_hh, out, write_states);
}